// round 1
// baseline (speedup 1.0000x reference)
#include <cuda_runtime.h>
#include <cuda_bf16.h>
#include <cstdint>

// ---------------- model dims ----------------
#define B_    8
#define L_    512
#define D_IN  128
#define D_MODEL 512
#define N_LAYERS 2
#define D_STATE 16
#define D_CONV  4
#define D_INNER 1024
#define DT_RANK 32
#define ML (B_ * L_)        // 4096 rows for all token-parallel GEMMs

// ---------------- scratch (allocation-free: __device__ globals) ----------------
__device__ float g_ha[ML * D_MODEL];         // 8 MB
__device__ float g_hb[ML * D_MODEL];         // 8 MB
__device__ float g_xz[ML * 2 * D_INNER];     // 32 MB
__device__ float g_xc[ML * D_INNER];         // 16 MB
__device__ float g_xdbl[ML * 64];            // 1 MB
__device__ float g_dt[ML * D_INNER];         // 16 MB
__device__ float g_y[ML * D_INNER];          // 16 MB
__device__ float g_hm[B_ * D_MODEL];

// ---------------- activations ----------------
__device__ __forceinline__ float act_silu(float v) {
    return v / (1.f + __expf(-v));
}
__device__ __forceinline__ float act_softplus(float v) {
    // log(1+exp(v)); stable for large v
    return (v > 20.f) ? v : log1pf(__expf(v));
}

// ---------------- GEMM: C[M,N] = A[M,lda(:K)] * W[N,K]^T (+bias)(+act) ----------------
// BM=128, BN=128, BK=16, 256 threads, 8x8 per thread.
#define BM 128
#define BN 128
#define BK 16

__global__ __launch_bounds__(256) void gemm_nt(
    const float* __restrict__ A, const float* __restrict__ W,
    const float* __restrict__ bias, float* __restrict__ C,
    int M, int N, int K, int lda, int act)
{
    __shared__ float As[BK][BM];
    __shared__ float Ws[BK][BN];

    const int bm = blockIdx.y * BM;
    const int bn = blockIdx.x * BN;
    const int tid = threadIdx.x;
    const int tr = tid >> 4;      // 0..15
    const int tc = tid & 15;      // 0..15

    float acc[8][8];
    #pragma unroll
    for (int i = 0; i < 8; i++)
        #pragma unroll
        for (int j = 0; j < 8; j++) acc[i][j] = 0.f;

    for (int k0 = 0; k0 < K; k0 += BK) {
        // Load A tile as float4 along K, transpose into As[k][m]
        #pragma unroll
        for (int t = tid; t < BM * (BK / 4); t += 256) {
            int i  = t >> 2;             // 0..127 row within tile
            int j4 = (t & 3) << 2;       // 0,4,8,12
            float4 v = make_float4(0.f, 0.f, 0.f, 0.f);
            int row = bm + i;
            if (row < M)
                v = *reinterpret_cast<const float4*>(&A[(size_t)row * lda + k0 + j4]);
            As[j4 + 0][i] = v.x; As[j4 + 1][i] = v.y;
            As[j4 + 2][i] = v.z; As[j4 + 3][i] = v.w;
        }
        #pragma unroll
        for (int t = tid; t < BN * (BK / 4); t += 256) {
            int i  = t >> 2;
            int j4 = (t & 3) << 2;
            float4 v = make_float4(0.f, 0.f, 0.f, 0.f);
            int row = bn + i;
            if (row < N)
                v = *reinterpret_cast<const float4*>(&W[(size_t)row * K + k0 + j4]);
            Ws[j4 + 0][i] = v.x; Ws[j4 + 1][i] = v.y;
            Ws[j4 + 2][i] = v.z; Ws[j4 + 3][i] = v.w;
        }
        __syncthreads();

        #pragma unroll
        for (int k = 0; k < BK; k++) {
            float a[8], w[8];
            float4 a0 = *reinterpret_cast<const float4*>(&As[k][tr * 8]);
            float4 a1 = *reinterpret_cast<const float4*>(&As[k][tr * 8 + 4]);
            float4 w0 = *reinterpret_cast<const float4*>(&Ws[k][tc * 8]);
            float4 w1 = *reinterpret_cast<const float4*>(&Ws[k][tc * 8 + 4]);
            a[0]=a0.x; a[1]=a0.y; a[2]=a0.z; a[3]=a0.w;
            a[4]=a1.x; a[5]=a1.y; a[6]=a1.z; a[7]=a1.w;
            w[0]=w0.x; w[1]=w0.y; w[2]=w0.z; w[3]=w0.w;
            w[4]=w1.x; w[5]=w1.y; w[6]=w1.z; w[7]=w1.w;
            #pragma unroll
            for (int i = 0; i < 8; i++)
                #pragma unroll
                for (int j = 0; j < 8; j++)
                    acc[i][j] = fmaf(a[i], w[j], acc[i][j]);
        }
        __syncthreads();
    }

    #pragma unroll
    for (int i = 0; i < 8; i++) {
        int row = bm + tr * 8 + i;
        if (row >= M) continue;
        #pragma unroll
        for (int j = 0; j < 8; j++) {
            int col = bn + tc * 8 + j;
            if (col >= N) continue;
            float v = acc[i][j];
            if (bias) v += bias[col];
            if (act == 1) v = act_softplus(v);
            else if (act == 2) v = fmaxf(v, 0.f);
            C[(size_t)row * N + col] = v;
        }
    }
}

// ---------------- causal depthwise conv1d + bias + SiLU ----------------
// xi = xz[..., 0:D_INNER]; out xc (B,L,D_INNER)
__global__ void conv_silu_kernel(const float* __restrict__ xz,
                                 const float* __restrict__ cw,  // (D_INNER, 4)
                                 const float* __restrict__ cb,  // (D_INNER)
                                 float* __restrict__ xc)
{
    int idx = blockIdx.x * blockDim.x + threadIdx.x;
    if (idx >= ML * D_INNER) return;
    int d = idx & (D_INNER - 1);
    int bl = idx >> 10;            // b*L + l
    int l = bl & (L_ - 1);
    int b = bl >> 9;

    float w0 = __ldg(&cw[d * 4 + 0]);
    float w1 = __ldg(&cw[d * 4 + 1]);
    float w2 = __ldg(&cw[d * 4 + 2]);
    float w3 = __ldg(&cw[d * 4 + 3]);
    float acc = __ldg(&cb[d]);

    const size_t rowstride = 2 * D_INNER;
    size_t base = ((size_t)b * L_) * rowstride + d;
    if (l >= 3) acc = fmaf(w0, xz[base + (size_t)(l - 3) * rowstride], acc);
    if (l >= 2) acc = fmaf(w1, xz[base + (size_t)(l - 2) * rowstride], acc);
    if (l >= 1) acc = fmaf(w2, xz[base + (size_t)(l - 1) * rowstride], acc);
    acc = fmaf(w3, xz[base + (size_t)l * rowstride], acc);

    xc[idx] = act_silu(acc);
}

// ---------------- selective scan (sequential over L), fused D-skip + gate ----------------
// one thread per (b, d); 16 states in registers.
__global__ void scan_kernel(const float* __restrict__ dt,    // (B,L,D_INNER)
                            const float* __restrict__ xc,    // (B,L,D_INNER)
                            const float* __restrict__ xdbl,  // (B,L,64): [.,32:48]=B, [.,48:64]=C
                            const float* __restrict__ xz,    // (B,L,2*D_INNER): z at +D_INNER
                            const float* __restrict__ A_log, // (D_INNER,16)
                            const float* __restrict__ Dm,    // (D_INNER)
                            float* __restrict__ y)           // (B,L,D_INNER)
{
    int d = blockIdx.x * blockDim.x + threadIdx.x;
    int b = blockIdx.y;
    if (d >= D_INNER) return;

    float Av[D_STATE];
    #pragma unroll
    for (int s = 0; s < D_STATE; s++) Av[s] = -__expf(A_log[d * D_STATE + s]);

    float h[D_STATE];
    #pragma unroll
    for (int s = 0; s < D_STATE; s++) h[s] = 0.f;

    const float Dd = __ldg(&Dm[d]);

    for (int l = 0; l < L_; l++) {
        size_t row = (size_t)b * L_ + l;
        float dtv = dt[row * D_INNER + d];
        float xv  = xc[row * D_INNER + d];
        float zv  = xz[row * 2 * D_INNER + D_INNER + d];
        const float* bc = xdbl + row * 64 + DT_RANK;   // B at [0:16), C at [16:32)

        float p = dtv * xv;
        float acc = 0.f;
        #pragma unroll
        for (int s = 0; s < D_STATE; s++) {
            float dA = __expf(dtv * Av[s]);
            float hs = fmaf(dA, h[s], p * __ldg(bc + s));
            h[s] = hs;
            acc = fmaf(hs, __ldg(bc + D_STATE + s), acc);
        }
        float yv = fmaf(xv, Dd, acc);
        y[row * D_INNER + d] = yv * act_silu(zv);
    }
}

// ---------------- mean over L ----------------
__global__ void mean_kernel(const float* __restrict__ h, float* __restrict__ hm)
{
    int i = blockIdx.x * blockDim.x + threadIdx.x;
    if (i >= B_ * D_MODEL) return;
    int b = i / D_MODEL, d = i % D_MODEL;
    float acc = 0.f;
    const float* p = h + (size_t)b * L_ * D_MODEL + d;
    for (int l = 0; l < L_; l++) acc += p[(size_t)l * D_MODEL];
    hm[i] = acc * (1.f / L_);
}

// ---------------- classifier head ----------------
__global__ void cls_kernel(const float* __restrict__ hm,
                           const float* __restrict__ w1, const float* __restrict__ b1,
                           const float* __restrict__ w2, const float* __restrict__ b2,
                           float* __restrict__ out)
{
    int b = blockIdx.x;      // 0..7
    int j = threadIdx.x;     // 0..63
    __shared__ float sh[64];
    float acc = __ldg(&b1[j]);
    const float* hv = hm + b * D_MODEL;
    const float* wv = w1 + j * D_MODEL;
    for (int k = 0; k < D_MODEL; k += 4) {
        float4 hh = *reinterpret_cast<const float4*>(&hv[k]);
        float4 ww = *reinterpret_cast<const float4*>(&wv[k]);
        acc = fmaf(hh.x, ww.x, acc);
        acc = fmaf(hh.y, ww.y, acc);
        acc = fmaf(hh.z, ww.z, acc);
        acc = fmaf(hh.w, ww.w, acc);
    }
    acc = fmaxf(acc, 0.f);
    sh[j] = acc * __ldg(&w2[j]);
    __syncthreads();
    if (j == 0) {
        float s = __ldg(&b2[0]);
        #pragma unroll
        for (int t = 0; t < 64; t++) s += sh[t];
        out[b] = s;
    }
}

// ---------------- launch ----------------
static inline dim3 gemm_grid(int M, int N) {
    return dim3((N + BN - 1) / BN, (M + BM - 1) / BM);
}

extern "C" void kernel_launch(void* const* d_in, const int* in_sizes, int n_in,
                              void* d_out, int out_size)
{
    const float* x          = (const float*)d_in[0];
    const float* proj_in_w  = (const float*)d_in[1];
    const float* proj_in_b  = (const float*)d_in[2];
    const float* in_proj_w  = (const float*)d_in[3];
    const float* conv_w     = (const float*)d_in[4];
    const float* conv_b     = (const float*)d_in[5];
    const float* x_proj_w   = (const float*)d_in[6];
    const float* dt_proj_w  = (const float*)d_in[7];
    const float* dt_proj_b  = (const float*)d_in[8];
    const float* A_log      = (const float*)d_in[9];
    const float* Dm         = (const float*)d_in[10];
    const float* out_proj_w = (const float*)d_in[11];
    const float* cls_w1     = (const float*)d_in[12];
    const float* cls_b1     = (const float*)d_in[13];
    const float* cls_w2     = (const float*)d_in[14];
    const float* cls_b2     = (const float*)d_in[15];

    void* p;
    cudaGetSymbolAddress(&p, g_ha);   float* ha   = (float*)p;
    cudaGetSymbolAddress(&p, g_hb);   float* hb   = (float*)p;
    cudaGetSymbolAddress(&p, g_xz);   float* xz   = (float*)p;
    cudaGetSymbolAddress(&p, g_xc);   float* xc   = (float*)p;
    cudaGetSymbolAddress(&p, g_xdbl); float* xdbl = (float*)p;
    cudaGetSymbolAddress(&p, g_dt);   float* dt   = (float*)p;
    cudaGetSymbolAddress(&p, g_y);    float* y    = (float*)p;
    cudaGetSymbolAddress(&p, g_hm);   float* hm   = (float*)p;

    // h = x @ proj_in_w^T + b   (4096 x 512, K=128)
    gemm_nt<<<gemm_grid(ML, D_MODEL), 256>>>(x, proj_in_w, proj_in_b, ha,
                                             ML, D_MODEL, D_IN, D_IN, 0);

    float* cur = ha;
    float* nxt = hb;
    for (int l = 0; l < N_LAYERS; l++) {
        const float* in_w  = in_proj_w  + (size_t)l * 2 * D_INNER * D_MODEL;
        const float* cw    = conv_w     + (size_t)l * D_INNER * D_CONV;
        const float* cb    = conv_b     + (size_t)l * D_INNER;
        const float* xp_w  = x_proj_w   + (size_t)l * 64 * D_INNER;
        const float* dt_w  = dt_proj_w  + (size_t)l * D_INNER * DT_RANK;
        const float* dt_b  = dt_proj_b  + (size_t)l * D_INNER;
        const float* Al    = A_log      + (size_t)l * D_INNER * D_STATE;
        const float* Dl    = Dm         + (size_t)l * D_INNER;
        const float* out_w = out_proj_w + (size_t)l * D_MODEL * D_INNER;

        // xz = h @ in_w^T   (4096 x 2048, K=512)
        gemm_nt<<<gemm_grid(ML, 2 * D_INNER), 256>>>(cur, in_w, nullptr, xz,
                                                     ML, 2 * D_INNER, D_MODEL, D_MODEL, 0);
        // depthwise conv + silu
        conv_silu_kernel<<<(ML * D_INNER) / 256, 256>>>(xz, cw, cb, xc);
        // x_dbl = xc @ xp_w^T   (4096 x 64, K=1024)
        gemm_nt<<<gemm_grid(ML, 64), 256>>>(xc, xp_w, nullptr, xdbl,
                                            ML, 64, D_INNER, D_INNER, 0);
        // dt = softplus(x_dbl[:, :32] @ dt_w^T + dt_b)   (4096 x 1024, K=32, lda=64)
        gemm_nt<<<gemm_grid(ML, D_INNER), 256>>>(xdbl, dt_w, dt_b, dt,
                                                 ML, D_INNER, DT_RANK, 64, 1);
        // selective scan + D skip + silu gate
        scan_kernel<<<dim3(D_INNER / 128, B_), 128>>>(dt, xc, xdbl, xz, Al, Dl, y);
        // h = y @ out_w^T   (4096 x 512, K=1024)
        gemm_nt<<<gemm_grid(ML, D_MODEL), 256>>>(y, out_w, nullptr, nxt,
                                                 ML, D_MODEL, D_INNER, D_INNER, 0);
        float* t = cur; cur = nxt; nxt = t;
    }

    mean_kernel<<<(B_ * D_MODEL + 255) / 256, 256>>>(cur, hm);
    cls_kernel<<<B_, 64>>>(hm, cls_w1, cls_b1, cls_w2, cls_b2, (float*)d_out);
}

// round 2
// speedup vs baseline: 2.3752x; 2.3752x over previous
#include <cuda_runtime.h>
#include <cuda_bf16.h>
#include <cstdint>

// ---------------- model dims ----------------
#define B_    8
#define L_    512
#define D_IN  128
#define D_MODEL 512
#define N_LAYERS 2
#define D_STATE 16
#define D_CONV  4
#define D_INNER 1024
#define DT_RANK 32
#define ML (B_ * L_)        // 4096 rows for all token-parallel GEMMs
#define KSPLIT 8            // split-K factor for x_proj

// ---------------- scratch (allocation-free: __device__ globals) ----------------
__device__ float g_ha[ML * D_MODEL];            // 8 MB
__device__ float g_hb[ML * D_MODEL];            // 8 MB
__device__ float g_xz[ML * 2 * D_INNER];        // 32 MB
__device__ float g_xc[ML * D_INNER];            // 16 MB
__device__ float g_xdbl[ML * 64];               // 1 MB
__device__ float g_xpart[KSPLIT * ML * 64];     // 8 MB
__device__ float g_dt[ML * D_INNER];            // 16 MB
__device__ float g_y[ML * D_INNER];             // 16 MB
__device__ float g_hpart[B_ * 8 * D_MODEL];     // 128 KB
__device__ float g_hm[B_ * D_MODEL];

// ---------------- activations ----------------
__device__ __forceinline__ float act_silu(float v) {
    return v / (1.f + __expf(-v));
}
__device__ __forceinline__ float act_softplus(float v) {
    return (v > 20.f) ? v : log1pf(__expf(v));
}

// =====================================================================
// GEMM: C[M,N] = A[M,:K] (row stride lda) * W[N,:K] (row stride ldw)^T
// Double-buffered smem, register-staged global loads, one sync/tile.
// Requires: M % 128 == 0, N % BN == 0, K % 16 == 0. No bounds checks.
// Split-K via gridDim.z: block z computes K-slice [z*K, (z+1)*K) of the
// full reduction (caller passes slice length as K and offsets via z);
// output goes to C + z*M*N.
// =====================================================================
#define GBM 128
#define GBK 16

template<int BN>
__global__ __launch_bounds__(256) void gemm_nt(
    const float* __restrict__ A, int lda,
    const float* __restrict__ W, int ldw,
    const float* __restrict__ bias, float* __restrict__ C,
    int M, int N, int K, int act)
{
    constexpr int TN = BN / 16;            // 8 or 4
    constexpr int WU = (BN * 4) / 256;     // W float4 loads per thread (2 or 1)

    __shared__ float As[2][GBK][GBM];
    __shared__ float Ws[2][GBK][BN];

    // split-K offsets (no-op when gridDim.z == 1)
    const int z = blockIdx.z;
    A += (size_t)z * K;
    W += (size_t)z * K;
    C += (size_t)z * M * N;

    const int bm = blockIdx.y * GBM;
    const int bn = blockIdx.x * BN;
    const int tid = threadIdx.x;
    const int tr = tid >> 4;               // 0..15 (row group)
    const int tc = tid & 15;               // 0..15 (col group)

    float acc[8][TN];
    #pragma unroll
    for (int i = 0; i < 8; i++)
        #pragma unroll
        for (int j = 0; j < TN; j++) acc[i][j] = 0.f;

    float4 ra[2], rw[WU];

    // precomputed load coords
    int ai[2], aj[2], wi[WU], wj[WU];
    #pragma unroll
    for (int u = 0; u < 2; u++) {
        int s = tid + u * 256;
        ai[u] = s >> 2; aj[u] = (s & 3) << 2;
    }
    #pragma unroll
    for (int u = 0; u < WU; u++) {
        int s = tid + u * 256;
        wi[u] = s >> 2; wj[u] = (s & 3) << 2;
    }

    const int nt = K / GBK;

    // prologue: tile 0
    #pragma unroll
    for (int u = 0; u < 2; u++)
        ra[u] = *reinterpret_cast<const float4*>(&A[(size_t)(bm + ai[u]) * lda + aj[u]]);
    #pragma unroll
    for (int u = 0; u < WU; u++)
        rw[u] = *reinterpret_cast<const float4*>(&W[(size_t)(bn + wi[u]) * ldw + wj[u]]);
    #pragma unroll
    for (int u = 0; u < 2; u++) {
        As[0][aj[u] + 0][ai[u]] = ra[u].x; As[0][aj[u] + 1][ai[u]] = ra[u].y;
        As[0][aj[u] + 2][ai[u]] = ra[u].z; As[0][aj[u] + 3][ai[u]] = ra[u].w;
    }
    #pragma unroll
    for (int u = 0; u < WU; u++) {
        Ws[0][wj[u] + 0][wi[u]] = rw[u].x; Ws[0][wj[u] + 1][wi[u]] = rw[u].y;
        Ws[0][wj[u] + 2][wi[u]] = rw[u].z; Ws[0][wj[u] + 3][wi[u]] = rw[u].w;
    }
    __syncthreads();

    for (int t = 0; t < nt; t++) {
        const int buf = t & 1;
        const bool more = (t + 1 < nt);
        if (more) {
            const int k0 = (t + 1) * GBK;
            #pragma unroll
            for (int u = 0; u < 2; u++)
                ra[u] = *reinterpret_cast<const float4*>(&A[(size_t)(bm + ai[u]) * lda + k0 + aj[u]]);
            #pragma unroll
            for (int u = 0; u < WU; u++)
                rw[u] = *reinterpret_cast<const float4*>(&W[(size_t)(bn + wi[u]) * ldw + k0 + wj[u]]);
        }

        #pragma unroll
        for (int k = 0; k < GBK; k++) {
            float a[8], w[TN];
            float4 a0 = *reinterpret_cast<const float4*>(&As[buf][k][tr * 8]);
            float4 a1 = *reinterpret_cast<const float4*>(&As[buf][k][tr * 8 + 4]);
            a[0]=a0.x; a[1]=a0.y; a[2]=a0.z; a[3]=a0.w;
            a[4]=a1.x; a[5]=a1.y; a[6]=a1.z; a[7]=a1.w;
            #pragma unroll
            for (int j4 = 0; j4 < TN; j4 += 4) {
                float4 w0 = *reinterpret_cast<const float4*>(&Ws[buf][k][tc * TN + j4]);
                w[j4+0]=w0.x; w[j4+1]=w0.y; w[j4+2]=w0.z; w[j4+3]=w0.w;
            }
            #pragma unroll
            for (int i = 0; i < 8; i++)
                #pragma unroll
                for (int j = 0; j < TN; j++)
                    acc[i][j] = fmaf(a[i], w[j], acc[i][j]);
        }

        if (more) {
            const int nbuf = buf ^ 1;
            #pragma unroll
            for (int u = 0; u < 2; u++) {
                As[nbuf][aj[u] + 0][ai[u]] = ra[u].x; As[nbuf][aj[u] + 1][ai[u]] = ra[u].y;
                As[nbuf][aj[u] + 2][ai[u]] = ra[u].z; As[nbuf][aj[u] + 3][ai[u]] = ra[u].w;
            }
            #pragma unroll
            for (int u = 0; u < WU; u++) {
                Ws[nbuf][wj[u] + 0][wi[u]] = rw[u].x; Ws[nbuf][wj[u] + 1][wi[u]] = rw[u].y;
                Ws[nbuf][wj[u] + 2][wi[u]] = rw[u].z; Ws[nbuf][wj[u] + 3][wi[u]] = rw[u].w;
            }
        }
        __syncthreads();
    }

    // epilogue: vectorized stores
    float bfrag[TN];
    #pragma unroll
    for (int j = 0; j < TN; j++)
        bfrag[j] = bias ? __ldg(&bias[bn + tc * TN + j]) : 0.f;

    #pragma unroll
    for (int i = 0; i < 8; i++) {
        const size_t row = bm + tr * 8 + i;
        #pragma unroll
        for (int j4 = 0; j4 < TN; j4 += 4) {
            float4 v;
            float* vv = &v.x;
            #pragma unroll
            for (int j = 0; j < 4; j++) {
                float u = acc[i][j4 + j] + bfrag[j4 + j];
                if (act == 1) u = act_softplus(u);
                vv[j] = u;
            }
            *reinterpret_cast<float4*>(&C[row * N + bn + tc * TN + j4]) = v;
        }
    }
}

// reduce split-K partials: out[i] = sum_z part[z*n + i]
__global__ void reduce_ksplit(const float* __restrict__ part, float* __restrict__ out, int n)
{
    int i = blockIdx.x * blockDim.x + threadIdx.x;
    if (i >= n) return;
    float acc = 0.f;
    #pragma unroll
    for (int zz = 0; zz < KSPLIT; zz++) acc += part[(size_t)zz * n + i];
    out[i] = acc;
}

// ---------------- causal depthwise conv1d + bias + SiLU ----------------
__global__ void conv_silu_kernel(const float* __restrict__ xz,
                                 const float* __restrict__ cw,
                                 const float* __restrict__ cb,
                                 float* __restrict__ xc)
{
    int idx = blockIdx.x * blockDim.x + threadIdx.x;
    if (idx >= ML * D_INNER) return;
    int d = idx & (D_INNER - 1);
    int bl = idx >> 10;
    int l = bl & (L_ - 1);
    int b = bl >> 9;

    float w0 = __ldg(&cw[d * 4 + 0]);
    float w1 = __ldg(&cw[d * 4 + 1]);
    float w2 = __ldg(&cw[d * 4 + 2]);
    float w3 = __ldg(&cw[d * 4 + 3]);
    float acc = __ldg(&cb[d]);

    const size_t rowstride = 2 * D_INNER;
    size_t base = ((size_t)b * L_) * rowstride + d;
    if (l >= 3) acc = fmaf(w0, xz[base + (size_t)(l - 3) * rowstride], acc);
    if (l >= 2) acc = fmaf(w1, xz[base + (size_t)(l - 2) * rowstride], acc);
    if (l >= 1) acc = fmaf(w2, xz[base + (size_t)(l - 1) * rowstride], acc);
    acc = fmaf(w3, xz[base + (size_t)l * rowstride], acc);

    xc[idx] = act_silu(acc);
}

// =====================================================================
// Selective scan: thread = (b, d), 16 states in regs, window of 8 steps.
// B/C rows staged in double-buffered smem; dt/xc/z register-prefetched.
// Fast path exploits A_s = (s+1)*A_0 (true for this model's A_log):
// one exp + depth-4 multiply tree instead of 16 exps per step.
// =====================================================================
__global__ __launch_bounds__(64) void scan_kernel(
    const float* __restrict__ dt, const float* __restrict__ xc,
    const float* __restrict__ xdbl, const float* __restrict__ xz,
    const float* __restrict__ A_log, const float* __restrict__ Dm,
    float* __restrict__ y)
{
    const int tid = threadIdx.x;
    const int d = blockIdx.x * 64 + tid;
    const int b = blockIdx.y;

    __shared__ float sBC[2][8][32];   // [.][iter][0:16)=B, [16:32)=C

    float Av[D_STATE];
    #pragma unroll
    for (int s = 0; s < D_STATE; s++) Av[s] = -__expf(__ldg(&A_log[d * D_STATE + s]));
    const float Av0 = Av[0];
    int fastl = 1;
    #pragma unroll
    for (int s = 1; s < D_STATE; s++) {
        float tgt = (s + 1) * Av0;
        fastl &= (fabsf(Av[s] - tgt) <= 1e-4f * fabsf(tgt)) ? 1 : 0;
    }
    const int fast = __syncthreads_and(fastl);

    float h[D_STATE];
    #pragma unroll
    for (int s = 0; s < D_STATE; s++) h[s] = 0.f;
    const float Dd = __ldg(&Dm[d]);
    const size_t rowb = (size_t)b * L_;

    float cdt[8], cxc[8], cz[8], ndt[8], nxc[8], nz[8];

    // smem fill: 64 threads <-> 64 float4 slots (8 rows x 8 quads)
    {
        int r = tid >> 3, q = tid & 7;
        float4 v = *reinterpret_cast<const float4*>(&xdbl[(rowb + r) * 64 + 32 + q * 4]);
        *reinterpret_cast<float4*>(&sBC[0][r][q * 4]) = v;
    }
    #pragma unroll
    for (int i = 0; i < 8; i++) {
        size_t row = rowb + i;
        cdt[i] = __ldg(&dt[row * D_INNER + d]);
        cxc[i] = __ldg(&xc[row * D_INNER + d]);
        cz[i]  = __ldg(&xz[row * 2 * D_INNER + D_INNER + d]);
    }
    __syncthreads();

    for (int w = 0; w < L_ / 8; w++) {
        const int slot = w & 1;
        if (w + 1 < L_ / 8) {
            int r = tid >> 3, q = tid & 7;
            float4 v = *reinterpret_cast<const float4*>(
                &xdbl[(rowb + (w + 1) * 8 + r) * 64 + 32 + q * 4]);
            *reinterpret_cast<float4*>(&sBC[slot ^ 1][r][q * 4]) = v;
            #pragma unroll
            for (int i = 0; i < 8; i++) {
                size_t row = rowb + (w + 1) * 8 + i;
                ndt[i] = __ldg(&dt[row * D_INNER + d]);
                nxc[i] = __ldg(&xc[row * D_INNER + d]);
                nz[i]  = __ldg(&xz[row * 2 * D_INNER + D_INNER + d]);
            }
        }

        #pragma unroll
        for (int i = 0; i < 8; i++) {
            const float dtv = cdt[i], xv = cxc[i], zv = cz[i];
            const float p = dtv * xv;
            const float* bc = sBC[slot][i];
            float acc0 = 0.f, acc1 = 0.f;
            if (fast) {
                const float q1 = __expf(dtv * Av0);
                const float q2 = q1 * q1, q3 = q2 * q1, q4 = q2 * q2;
                const float q5 = q4 * q1, q6 = q4 * q2, q7 = q4 * q3, q8 = q4 * q4;
                const float dA[16] = {q1, q2, q3, q4, q5, q6, q7, q8,
                                      q8*q1, q8*q2, q8*q3, q8*q4, q8*q5, q8*q6, q8*q7, q8*q8};
                #pragma unroll
                for (int s = 0; s < D_STATE; s++) {
                    float hs = fmaf(dA[s], h[s], p * bc[s]);
                    h[s] = hs;
                    if (s & 1) acc1 = fmaf(hs, bc[16 + s], acc1);
                    else       acc0 = fmaf(hs, bc[16 + s], acc0);
                }
            } else {
                #pragma unroll
                for (int s = 0; s < D_STATE; s++) {
                    float hs = fmaf(__expf(dtv * Av[s]), h[s], p * bc[s]);
                    h[s] = hs;
                    if (s & 1) acc1 = fmaf(hs, bc[16 + s], acc1);
                    else       acc0 = fmaf(hs, bc[16 + s], acc0);
                }
            }
            const size_t row = rowb + w * 8 + i;
            y[row * D_INNER + d] = fmaf(xv, Dd, acc0 + acc1) * act_silu(zv);
        }

        #pragma unroll
        for (int i = 0; i < 8; i++) { cdt[i] = ndt[i]; cxc[i] = nxc[i]; cz[i] = nz[i]; }
        __syncthreads();
    }
}

// ---------------- mean over L (2-stage) ----------------
__global__ void mean_part_kernel(const float* __restrict__ h, float* __restrict__ part)
{
    int b = blockIdx.x, lc = blockIdx.y, d = threadIdx.x;  // 512 threads
    float acc = 0.f;
    #pragma unroll 8
    for (int l = lc * 64; l < lc * 64 + 64; l++)
        acc += h[((size_t)b * L_ + l) * D_MODEL + d];
    part[(b * 8 + lc) * D_MODEL + d] = acc;
}
__global__ void mean_fin_kernel(const float* __restrict__ part, float* __restrict__ hm)
{
    int i = blockIdx.x * blockDim.x + threadIdx.x;
    if (i >= B_ * D_MODEL) return;
    int b = i / D_MODEL, d = i % D_MODEL;
    float acc = 0.f;
    #pragma unroll
    for (int c = 0; c < 8; c++) acc += part[(b * 8 + c) * D_MODEL + d];
    hm[i] = acc * (1.f / L_);
}

// ---------------- classifier head ----------------
__global__ void cls_kernel(const float* __restrict__ hm,
                           const float* __restrict__ w1, const float* __restrict__ b1,
                           const float* __restrict__ w2, const float* __restrict__ b2,
                           float* __restrict__ out)
{
    int b = blockIdx.x;
    int j = threadIdx.x;
    __shared__ float sh[64];
    float acc = __ldg(&b1[j]);
    const float* hv = hm + b * D_MODEL;
    const float* wv = w1 + j * D_MODEL;
    for (int k = 0; k < D_MODEL; k += 4) {
        float4 hh = *reinterpret_cast<const float4*>(&hv[k]);
        float4 ww = *reinterpret_cast<const float4*>(&wv[k]);
        acc = fmaf(hh.x, ww.x, acc);
        acc = fmaf(hh.y, ww.y, acc);
        acc = fmaf(hh.z, ww.z, acc);
        acc = fmaf(hh.w, ww.w, acc);
    }
    acc = fmaxf(acc, 0.f);
    sh[j] = acc * __ldg(&w2[j]);
    __syncthreads();
    if (j == 0) {
        float s = __ldg(&b2[0]);
        #pragma unroll
        for (int t = 0; t < 64; t++) s += sh[t];
        out[b] = s;
    }
}

// ---------------- launch ----------------
extern "C" void kernel_launch(void* const* d_in, const int* in_sizes, int n_in,
                              void* d_out, int out_size)
{
    const float* x          = (const float*)d_in[0];
    const float* proj_in_w  = (const float*)d_in[1];
    const float* proj_in_b  = (const float*)d_in[2];
    const float* in_proj_w  = (const float*)d_in[3];
    const float* conv_w     = (const float*)d_in[4];
    const float* conv_b     = (const float*)d_in[5];
    const float* x_proj_w   = (const float*)d_in[6];
    const float* dt_proj_w  = (const float*)d_in[7];
    const float* dt_proj_b  = (const float*)d_in[8];
    const float* A_log      = (const float*)d_in[9];
    const float* Dm         = (const float*)d_in[10];
    const float* out_proj_w = (const float*)d_in[11];
    const float* cls_w1     = (const float*)d_in[12];
    const float* cls_b1     = (const float*)d_in[13];
    const float* cls_w2     = (const float*)d_in[14];
    const float* cls_b2     = (const float*)d_in[15];

    void* p;
    cudaGetSymbolAddress(&p, g_ha);    float* ha    = (float*)p;
    cudaGetSymbolAddress(&p, g_hb);    float* hb    = (float*)p;
    cudaGetSymbolAddress(&p, g_xz);    float* xz    = (float*)p;
    cudaGetSymbolAddress(&p, g_xc);    float* xc    = (float*)p;
    cudaGetSymbolAddress(&p, g_xdbl);  float* xdbl  = (float*)p;
    cudaGetSymbolAddress(&p, g_xpart); float* xpart = (float*)p;
    cudaGetSymbolAddress(&p, g_dt);    float* dtb   = (float*)p;
    cudaGetSymbolAddress(&p, g_y);     float* y     = (float*)p;
    cudaGetSymbolAddress(&p, g_hpart); float* hpart = (float*)p;
    cudaGetSymbolAddress(&p, g_hm);    float* hm    = (float*)p;

    // h = x @ proj_in_w^T + b   (4096 x 512, K=128)
    gemm_nt<128><<<dim3(D_MODEL / 128, ML / GBM), 256>>>(
        x, D_IN, proj_in_w, D_IN, proj_in_b, ha, ML, D_MODEL, D_IN, 0);

    float* cur = ha;
    float* nxt = hb;
    for (int l = 0; l < N_LAYERS; l++) {
        const float* in_w  = in_proj_w  + (size_t)l * 2 * D_INNER * D_MODEL;
        const float* cw    = conv_w     + (size_t)l * D_INNER * D_CONV;
        const float* cb    = conv_b     + (size_t)l * D_INNER;
        const float* xp_w  = x_proj_w   + (size_t)l * 64 * D_INNER;
        const float* dt_w  = dt_proj_w  + (size_t)l * D_INNER * DT_RANK;
        const float* dt_b  = dt_proj_b  + (size_t)l * D_INNER;
        const float* Al    = A_log      + (size_t)l * D_INNER * D_STATE;
        const float* Dl    = Dm         + (size_t)l * D_INNER;
        const float* out_w = out_proj_w + (size_t)l * D_MODEL * D_INNER;

        // xz = h @ in_w^T   (4096 x 2048, K=512)
        gemm_nt<128><<<dim3(2 * D_INNER / 128, ML / GBM), 256>>>(
            cur, D_MODEL, in_w, D_MODEL, nullptr, xz, ML, 2 * D_INNER, D_MODEL, 0);
        // depthwise conv + silu
        conv_silu_kernel<<<(ML * D_INNER) / 256, 256>>>(xz, cw, cb, xc);
        // x_dbl = xc @ xp_w^T   (4096 x 64, K=1024) -- split-K over gridDim.z
        gemm_nt<64><<<dim3(1, ML / GBM, KSPLIT), 256>>>(
            xc, D_INNER, xp_w, D_INNER, nullptr, xpart, ML, 64, D_INNER / KSPLIT, 0);
        reduce_ksplit<<<(ML * 64 + 255) / 256, 256>>>(xpart, xdbl, ML * 64);
        // dt = softplus(x_dbl[:, :32] @ dt_w^T + dt_b)   (4096 x 1024, K=32, lda=64)
        gemm_nt<128><<<dim3(D_INNER / 128, ML / GBM), 256>>>(
            xdbl, 64, dt_w, DT_RANK, dt_b, dtb, ML, D_INNER, DT_RANK, 1);
        // selective scan + D skip + silu gate
        scan_kernel<<<dim3(D_INNER / 64, B_), 64>>>(dtb, xc, xdbl, xz, Al, Dl, y);
        // h = y @ out_w^T   (4096 x 512, K=1024)
        gemm_nt<128><<<dim3(D_MODEL / 128, ML / GBM), 256>>>(
            y, D_INNER, out_w, D_INNER, nullptr, nxt, ML, D_MODEL, D_INNER, 0);
        float* t = cur; cur = nxt; nxt = t;
    }

    mean_part_kernel<<<dim3(B_, 8), D_MODEL>>>(cur, hpart);
    mean_fin_kernel<<<(B_ * D_MODEL + 255) / 256, 256>>>(hpart, hm);
    cls_kernel<<<B_, 64>>>(hm, cls_w1, cls_b1, cls_w2, cls_b2, (float*)d_out);
}

// round 4
// speedup vs baseline: 3.9561x; 1.6656x over previous
#include <cuda_runtime.h>
#include <cuda_bf16.h>
#include <cstdint>

// ---------------- model dims ----------------
#define B_    8
#define L_    512
#define D_IN  128
#define D_MODEL 512
#define N_LAYERS 2
#define D_STATE 16
#define D_CONV  4
#define D_INNER 1024
#define DT_RANK 32
#define ML (B_ * L_)
#define KSPLIT 8

// ---------------- scratch ----------------
__device__ float g_ha[ML * D_MODEL];
__device__ float g_hb[ML * D_MODEL];
__device__ float g_xz[ML * 2 * D_INNER];
__device__ float g_xc[ML * D_INNER];
__device__ float g_xdbl[ML * 64];
__device__ float g_xpart[KSPLIT * ML * 64];
__device__ float g_dt[ML * D_INNER];
__device__ float g_y[ML * D_INNER];
__device__ float g_hpart[B_ * 8 * D_MODEL];
__device__ float g_hm[B_ * D_MODEL];

__device__ __forceinline__ float act_silu(float v) { return v / (1.f + __expf(-v)); }
__device__ __forceinline__ float act_softplus(float v) { return (v > 20.f) ? v : log1pf(__expf(v)); }

// =====================================================================
// mma.sync / ldmatrix helpers (arch-generic PTX; HMMA on tensor pipe)
// =====================================================================
__device__ __forceinline__ void ldsm_x4(uint32_t* r, uint32_t addr) {
    asm volatile("ldmatrix.sync.aligned.m8n8.x4.shared.b16 {%0,%1,%2,%3}, [%4];"
                 : "=r"(r[0]), "=r"(r[1]), "=r"(r[2]), "=r"(r[3]) : "r"(addr));
}

__device__ __forceinline__ void mma16816(float* c, const uint32_t* a, const uint32_t* b) {
    asm volatile(
        "mma.sync.aligned.m16n8k16.row.col.f32.bf16.bf16.f32 "
        "{%0,%1,%2,%3}, {%4,%5,%6,%7}, {%8,%9}, {%0,%1,%2,%3};"
        : "+f"(c[0]), "+f"(c[1]), "+f"(c[2]), "+f"(c[3])
        : "r"(a[0]), "r"(a[1]), "r"(a[2]), "r"(a[3]), "r"(b[0]), "r"(b[1]));
}

// fp32 float4 -> bf16 hi/lo (4+4 bf16 = 8+8 bytes) into swizzled smem
__device__ __forceinline__ void tc_cvt_store(char* hi, char* lo, uint32_t sw, float4 v) {
    __nv_bfloat162 h0 = __floats2bfloat162_rn(v.x, v.y);
    __nv_bfloat162 h1 = __floats2bfloat162_rn(v.z, v.w);
    float rx = v.x - __bfloat162float(h0.x);
    float ry = v.y - __bfloat162float(h0.y);
    float rz = v.z - __bfloat162float(h1.x);
    float rw = v.w - __bfloat162float(h1.y);
    __nv_bfloat162 l0 = __floats2bfloat162_rn(rx, ry);
    __nv_bfloat162 l1 = __floats2bfloat162_rn(rz, rw);
    *reinterpret_cast<uint2*>(hi + sw) =
        make_uint2(*reinterpret_cast<const uint32_t*>(&h0), *reinterpret_cast<const uint32_t*>(&h1));
    *reinterpret_cast<uint2*>(lo + sw) =
        make_uint2(*reinterpret_cast<const uint32_t*>(&l0), *reinterpret_cast<const uint32_t*>(&l1));
}

// =====================================================================
// Tensor-core GEMM via mma.sync: C[M,N] = A[M,:K]*W[N,:K]^T (+bias),
// fp32 via bf16 hi/lo split (3 MMAs). CTA 128x128, warp 64x32, K-chunk 64.
// Requires M%128==0, N%128==0, K%64==0.
// smem (64KB, single buffer): A_hi @0, A_lo @16K, W_hi @32K, W_lo @48K;
// each is 128 rows x 128B (64 bf16), SW128 swizzled.
// =====================================================================
#define MMA_SMEM_BYTES 65536

__global__ __launch_bounds__(256) void gemm_mma(
    const float* __restrict__ A, int lda,
    const float* __restrict__ W, int ldw,
    const float* __restrict__ bias, float* __restrict__ C,
    int N, int K)
{
    extern __shared__ char smem[];
    const uint32_t sbase = (uint32_t)__cvta_generic_to_shared(smem);
    const int tid = threadIdx.x;
    const int lane = tid & 31;
    const int wid = tid >> 5;
    const int wm = wid >> 2;           // 0..1 : 64-row half
    const int wn = wid & 3;            // 0..3 : 32-col quarter
    const int bm = blockIdx.y * 128;
    const int bn = blockIdx.x * 128;

    char* aHi = smem;
    char* aLo = smem + 16384;
    char* wHi = smem + 32768;
    char* wLo = smem + 49152;

    // ---- fill coords: idx = u*256+tid -> row (0..127), q (float4 slot 0..15)
    int rr[8], qq[8];
    uint32_t sws[8];
    #pragma unroll
    for (int u = 0; u < 8; u++) {
        int idx = u * 256 + tid;
        rr[u] = idx >> 4;
        qq[u] = idx & 15;
        uint32_t off = (uint32_t)(rr[u] * 128 + qq[u] * 8);
        sws[u] = off ^ ((off >> 3) & 0x70);
    }

    // ---- fragment lane addressing (SW128: xor term = (row&7)<<4)
    const int l7 = lane & 7;
    const uint32_t xorv = (uint32_t)l7 << 4;
    const int a_row = wm * 64 + l7 + ((lane >> 3) & 1) * 8;      // + i*16
    const uint32_t a_kb = (uint32_t)((lane >> 4) & 1) * 16;
    const int b_row = wn * 32 + ((lane >> 4) & 1) * 8 + l7;      // + jj*16
    const uint32_t b_kb = (uint32_t)((lane >> 3) & 1) * 16;

    float acc[4][4][4];
    #pragma unroll
    for (int i = 0; i < 4; i++)
        #pragma unroll
        for (int j = 0; j < 4; j++)
            #pragma unroll
            for (int r = 0; r < 4; r++) acc[i][j][r] = 0.f;

    float4 sa[8], sw_[8];
    const int nt = K / 64;

    // prologue: chunk 0
    #pragma unroll
    for (int u = 0; u < 8; u++) {
        sa[u]  = *reinterpret_cast<const float4*>(&A[(size_t)(bm + rr[u]) * lda + qq[u] * 4]);
        sw_[u] = *reinterpret_cast<const float4*>(&W[(size_t)(bn + rr[u]) * ldw + qq[u] * 4]);
    }
    #pragma unroll
    for (int u = 0; u < 8; u++) {
        tc_cvt_store(aHi, aLo, sws[u], sa[u]);
        tc_cvt_store(wHi, wLo, sws[u], sw_[u]);
    }
    __syncthreads();

    for (int t = 0; t < nt; t++) {
        const bool more = (t + 1 < nt);
        if (more) {
            const int k0 = (t + 1) * 64;
            #pragma unroll
            for (int u = 0; u < 8; u++) {
                sa[u]  = *reinterpret_cast<const float4*>(&A[(size_t)(bm + rr[u]) * lda + k0 + qq[u] * 4]);
                sw_[u] = *reinterpret_cast<const float4*>(&W[(size_t)(bn + rr[u]) * ldw + k0 + qq[u] * 4]);
            }
        }

        // compute: 4 k16 steps over current chunk
        #pragma unroll
        for (int kk = 0; kk < 4; kk++) {
            const uint32_t koff_a = ((uint32_t)(kk * 32) + a_kb) ^ xorv;
            const uint32_t koff_b = ((uint32_t)(kk * 32) + b_kb) ^ xorv;
            uint32_t ah[4][4], al[4][4], bh[2][4], bl[2][4];
            #pragma unroll
            for (int i = 0; i < 4; i++) {
                uint32_t ad = sbase + (uint32_t)((a_row + i * 16) * 128) + koff_a;
                ldsm_x4(ah[i], ad);
                ldsm_x4(al[i], ad + 16384);
            }
            #pragma unroll
            for (int jj = 0; jj < 2; jj++) {
                uint32_t bd = sbase + 32768 + (uint32_t)((b_row + jj * 16) * 128) + koff_b;
                ldsm_x4(bh[jj], bd);
                ldsm_x4(bl[jj], bd + 16384);
            }
            #pragma unroll
            for (int i = 0; i < 4; i++) {
                #pragma unroll
                for (int j = 0; j < 4; j++) {
                    const uint32_t* bhp = &bh[j >> 1][(j & 1) * 2];
                    const uint32_t* blp = &bl[j >> 1][(j & 1) * 2];
                    mma16816(acc[i][j], ah[i], bhp);
                    mma16816(acc[i][j], ah[i], blp);
                    mma16816(acc[i][j], al[i], bhp);
                }
            }
        }

        if (more) {
            __syncthreads();
            #pragma unroll
            for (int u = 0; u < 8; u++) {
                tc_cvt_store(aHi, aLo, sws[u], sa[u]);
                tc_cvt_store(wHi, wLo, sws[u], sw_[u]);
            }
            __syncthreads();
        }
    }

    // ---- epilogue: c0,c1 -> (row g, col 2t,2t+1); c2,c3 -> (row g+8)
    const int g = lane >> 2;
    const int t4 = lane & 3;
    #pragma unroll
    for (int i = 0; i < 4; i++) {
        const int r0 = bm + wm * 64 + i * 16 + g;
        const int r1 = r0 + 8;
        #pragma unroll
        for (int j = 0; j < 4; j++) {
            const int col = bn + wn * 32 + j * 8 + t4 * 2;
            const float b0 = bias ? __ldg(&bias[col]) : 0.f;
            const float b1 = bias ? __ldg(&bias[col + 1]) : 0.f;
            float2 v0 = make_float2(acc[i][j][0] + b0, acc[i][j][1] + b1);
            float2 v1 = make_float2(acc[i][j][2] + b0, acc[i][j][3] + b1);
            *reinterpret_cast<float2*>(&C[(size_t)r0 * N + col]) = v0;
            *reinterpret_cast<float2*>(&C[(size_t)r1 * N + col]) = v1;
        }
    }
}

// =====================================================================
// SIMT GEMM (x_proj split-K, dt_proj)
// =====================================================================
#define GBM 128
#define GBK 16

template<int BN>
__global__ __launch_bounds__(256) void gemm_nt(
    const float* __restrict__ A, int lda,
    const float* __restrict__ W, int ldw,
    const float* __restrict__ bias, float* __restrict__ C,
    int M, int N, int K, int act)
{
    constexpr int TN = BN / 16;
    constexpr int WU = (BN * 4) / 256;

    __shared__ float As[2][GBK][GBM];
    __shared__ float Ws[2][GBK][BN];

    const int z = blockIdx.z;
    A += (size_t)z * K;
    W += (size_t)z * K;
    C += (size_t)z * M * N;

    const int bm = blockIdx.y * GBM;
    const int bn = blockIdx.x * BN;
    const int tid = threadIdx.x;
    const int tr = tid >> 4;
    const int tc = tid & 15;

    float acc[8][TN];
    #pragma unroll
    for (int i = 0; i < 8; i++)
        #pragma unroll
        for (int j = 0; j < TN; j++) acc[i][j] = 0.f;

    float4 ra[2], rw[WU];
    int ai[2], aj[2], wi[WU], wj[WU];
    #pragma unroll
    for (int u = 0; u < 2; u++) { int s = tid + u * 256; ai[u] = s >> 2; aj[u] = (s & 3) << 2; }
    #pragma unroll
    for (int u = 0; u < WU; u++) { int s = tid + u * 256; wi[u] = s >> 2; wj[u] = (s & 3) << 2; }

    const int nt = K / GBK;

    #pragma unroll
    for (int u = 0; u < 2; u++)
        ra[u] = *reinterpret_cast<const float4*>(&A[(size_t)(bm + ai[u]) * lda + aj[u]]);
    #pragma unroll
    for (int u = 0; u < WU; u++)
        rw[u] = *reinterpret_cast<const float4*>(&W[(size_t)(bn + wi[u]) * ldw + wj[u]]);
    #pragma unroll
    for (int u = 0; u < 2; u++) {
        As[0][aj[u] + 0][ai[u]] = ra[u].x; As[0][aj[u] + 1][ai[u]] = ra[u].y;
        As[0][aj[u] + 2][ai[u]] = ra[u].z; As[0][aj[u] + 3][ai[u]] = ra[u].w;
    }
    #pragma unroll
    for (int u = 0; u < WU; u++) {
        Ws[0][wj[u] + 0][wi[u]] = rw[u].x; Ws[0][wj[u] + 1][wi[u]] = rw[u].y;
        Ws[0][wj[u] + 2][wi[u]] = rw[u].z; Ws[0][wj[u] + 3][wi[u]] = rw[u].w;
    }
    __syncthreads();

    for (int t = 0; t < nt; t++) {
        const int buf = t & 1;
        const bool more = (t + 1 < nt);
        if (more) {
            const int k0 = (t + 1) * GBK;
            #pragma unroll
            for (int u = 0; u < 2; u++)
                ra[u] = *reinterpret_cast<const float4*>(&A[(size_t)(bm + ai[u]) * lda + k0 + aj[u]]);
            #pragma unroll
            for (int u = 0; u < WU; u++)
                rw[u] = *reinterpret_cast<const float4*>(&W[(size_t)(bn + wi[u]) * ldw + k0 + wj[u]]);
        }

        #pragma unroll
        for (int k = 0; k < GBK; k++) {
            float a[8], w[TN];
            float4 a0 = *reinterpret_cast<const float4*>(&As[buf][k][tr * 8]);
            float4 a1 = *reinterpret_cast<const float4*>(&As[buf][k][tr * 8 + 4]);
            a[0]=a0.x; a[1]=a0.y; a[2]=a0.z; a[3]=a0.w;
            a[4]=a1.x; a[5]=a1.y; a[6]=a1.z; a[7]=a1.w;
            #pragma unroll
            for (int j4 = 0; j4 < TN; j4 += 4) {
                float4 w0 = *reinterpret_cast<const float4*>(&Ws[buf][k][tc * TN + j4]);
                w[j4+0]=w0.x; w[j4+1]=w0.y; w[j4+2]=w0.z; w[j4+3]=w0.w;
            }
            #pragma unroll
            for (int i = 0; i < 8; i++)
                #pragma unroll
                for (int j = 0; j < TN; j++)
                    acc[i][j] = fmaf(a[i], w[j], acc[i][j]);
        }

        if (more) {
            const int nbuf = buf ^ 1;
            #pragma unroll
            for (int u = 0; u < 2; u++) {
                As[nbuf][aj[u] + 0][ai[u]] = ra[u].x; As[nbuf][aj[u] + 1][ai[u]] = ra[u].y;
                As[nbuf][aj[u] + 2][ai[u]] = ra[u].z; As[nbuf][aj[u] + 3][ai[u]] = ra[u].w;
            }
            #pragma unroll
            for (int u = 0; u < WU; u++) {
                Ws[nbuf][wj[u] + 0][wi[u]] = rw[u].x; Ws[nbuf][wj[u] + 1][wi[u]] = rw[u].y;
                Ws[nbuf][wj[u] + 2][wi[u]] = rw[u].z; Ws[nbuf][wj[u] + 3][wi[u]] = rw[u].w;
            }
        }
        __syncthreads();
    }

    float bfrag[TN];
    #pragma unroll
    for (int j = 0; j < TN; j++)
        bfrag[j] = bias ? __ldg(&bias[bn + tc * TN + j]) : 0.f;

    #pragma unroll
    for (int i = 0; i < 8; i++) {
        const size_t row = bm + tr * 8 + i;
        #pragma unroll
        for (int j4 = 0; j4 < TN; j4 += 4) {
            float4 v;
            float* vv = &v.x;
            #pragma unroll
            for (int j = 0; j < 4; j++) {
                float u = acc[i][j4 + j] + bfrag[j4 + j];
                if (act == 1) u = act_softplus(u);
                vv[j] = u;
            }
            *reinterpret_cast<float4*>(&C[row * N + bn + tc * TN + j4]) = v;
        }
    }
}

__global__ void reduce_ksplit(const float* __restrict__ part, float* __restrict__ out, int n)
{
    int i = blockIdx.x * blockDim.x + threadIdx.x;
    if (i >= n) return;
    float acc = 0.f;
    #pragma unroll
    for (int zz = 0; zz < KSPLIT; zz++) acc += part[(size_t)zz * n + i];
    out[i] = acc;
}

// ---------------- causal depthwise conv1d + bias + SiLU ----------------
__global__ void conv_silu_kernel(const float* __restrict__ xz,
                                 const float* __restrict__ cw,
                                 const float* __restrict__ cb,
                                 float* __restrict__ xc)
{
    int idx = blockIdx.x * blockDim.x + threadIdx.x;
    if (idx >= ML * D_INNER) return;
    int d = idx & (D_INNER - 1);
    int bl = idx >> 10;
    int l = bl & (L_ - 1);
    int b = bl >> 9;

    float w0 = __ldg(&cw[d * 4 + 0]);
    float w1 = __ldg(&cw[d * 4 + 1]);
    float w2 = __ldg(&cw[d * 4 + 2]);
    float w3 = __ldg(&cw[d * 4 + 3]);
    float acc = __ldg(&cb[d]);

    const size_t rowstride = 2 * D_INNER;
    size_t base = ((size_t)b * L_) * rowstride + d;
    if (l >= 3) acc = fmaf(w0, xz[base + (size_t)(l - 3) * rowstride], acc);
    if (l >= 2) acc = fmaf(w1, xz[base + (size_t)(l - 2) * rowstride], acc);
    if (l >= 1) acc = fmaf(w2, xz[base + (size_t)(l - 1) * rowstride], acc);
    acc = fmaf(w3, xz[base + (size_t)l * rowstride], acc);

    xc[idx] = act_silu(acc);
}

// ---------------- selective scan ----------------
__global__ __launch_bounds__(64) void scan_kernel(
    const float* __restrict__ dt, const float* __restrict__ xc,
    const float* __restrict__ xdbl, const float* __restrict__ xz,
    const float* __restrict__ A_log, const float* __restrict__ Dm,
    float* __restrict__ y)
{
    const int tid = threadIdx.x;
    const int d = blockIdx.x * 64 + tid;
    const int b = blockIdx.y;

    __shared__ float sBC[2][8][32];

    float Av[D_STATE];
    #pragma unroll
    for (int s = 0; s < D_STATE; s++) Av[s] = -__expf(__ldg(&A_log[d * D_STATE + s]));
    const float Av0 = Av[0];
    int fastl = 1;
    #pragma unroll
    for (int s = 1; s < D_STATE; s++) {
        float tgt = (s + 1) * Av0;
        fastl &= (fabsf(Av[s] - tgt) <= 1e-4f * fabsf(tgt)) ? 1 : 0;
    }
    const int fast = __syncthreads_and(fastl);

    float h[D_STATE];
    #pragma unroll
    for (int s = 0; s < D_STATE; s++) h[s] = 0.f;
    const float Dd = __ldg(&Dm[d]);
    const size_t rowb = (size_t)b * L_;

    float cdt[8], cxc[8], cz[8], ndt[8], nxc[8], nz[8];

    {
        int r = tid >> 3, q = tid & 7;
        float4 v = *reinterpret_cast<const float4*>(&xdbl[(rowb + r) * 64 + 32 + q * 4]);
        *reinterpret_cast<float4*>(&sBC[0][r][q * 4]) = v;
    }
    #pragma unroll
    for (int i = 0; i < 8; i++) {
        size_t row = rowb + i;
        cdt[i] = __ldg(&dt[row * D_INNER + d]);
        cxc[i] = __ldg(&xc[row * D_INNER + d]);
        cz[i]  = __ldg(&xz[row * 2 * D_INNER + D_INNER + d]);
    }
    __syncthreads();

    for (int w = 0; w < L_ / 8; w++) {
        const int slot = w & 1;
        if (w + 1 < L_ / 8) {
            int r = tid >> 3, q = tid & 7;
            float4 v = *reinterpret_cast<const float4*>(
                &xdbl[(rowb + (w + 1) * 8 + r) * 64 + 32 + q * 4]);
            *reinterpret_cast<float4*>(&sBC[slot ^ 1][r][q * 4]) = v;
            #pragma unroll
            for (int i = 0; i < 8; i++) {
                size_t row = rowb + (w + 1) * 8 + i;
                ndt[i] = __ldg(&dt[row * D_INNER + d]);
                nxc[i] = __ldg(&xc[row * D_INNER + d]);
                nz[i]  = __ldg(&xz[row * 2 * D_INNER + D_INNER + d]);
            }
        }

        #pragma unroll
        for (int i = 0; i < 8; i++) {
            const float dtv = cdt[i], xv = cxc[i], zv = cz[i];
            const float p = dtv * xv;
            const float* bc = sBC[slot][i];
            float acc0 = 0.f, acc1 = 0.f;
            if (fast) {
                const float q1 = __expf(dtv * Av0);
                const float q2 = q1 * q1, q3 = q2 * q1, q4 = q2 * q2;
                const float q5 = q4 * q1, q6 = q4 * q2, q7 = q4 * q3, q8 = q4 * q4;
                const float dA[16] = {q1, q2, q3, q4, q5, q6, q7, q8,
                                      q8*q1, q8*q2, q8*q3, q8*q4, q8*q5, q8*q6, q8*q7, q8*q8};
                #pragma unroll
                for (int s = 0; s < D_STATE; s++) {
                    float hs = fmaf(dA[s], h[s], p * bc[s]);
                    h[s] = hs;
                    if (s & 1) acc1 = fmaf(hs, bc[16 + s], acc1);
                    else       acc0 = fmaf(hs, bc[16 + s], acc0);
                }
            } else {
                #pragma unroll
                for (int s = 0; s < D_STATE; s++) {
                    float hs = fmaf(__expf(dtv * Av[s]), h[s], p * bc[s]);
                    h[s] = hs;
                    if (s & 1) acc1 = fmaf(hs, bc[16 + s], acc1);
                    else       acc0 = fmaf(hs, bc[16 + s], acc0);
                }
            }
            const size_t row = rowb + w * 8 + i;
            y[row * D_INNER + d] = fmaf(xv, Dd, acc0 + acc1) * act_silu(zv);
        }

        #pragma unroll
        for (int i = 0; i < 8; i++) { cdt[i] = ndt[i]; cxc[i] = nxc[i]; cz[i] = nz[i]; }
        __syncthreads();
    }
}

// ---------------- mean over L (2-stage) ----------------
__global__ void mean_part_kernel(const float* __restrict__ h, float* __restrict__ part)
{
    int b = blockIdx.x, lc = blockIdx.y, d = threadIdx.x;
    float acc = 0.f;
    #pragma unroll 8
    for (int l = lc * 64; l < lc * 64 + 64; l++)
        acc += h[((size_t)b * L_ + l) * D_MODEL + d];
    part[(b * 8 + lc) * D_MODEL + d] = acc;
}
__global__ void mean_fin_kernel(const float* __restrict__ part, float* __restrict__ hm)
{
    int i = blockIdx.x * blockDim.x + threadIdx.x;
    if (i >= B_ * D_MODEL) return;
    int b = i / D_MODEL, d = i % D_MODEL;
    float acc = 0.f;
    #pragma unroll
    for (int c = 0; c < 8; c++) acc += part[(b * 8 + c) * D_MODEL + d];
    hm[i] = acc * (1.f / L_);
}

// ---------------- classifier head ----------------
__global__ void cls_kernel(const float* __restrict__ hm,
                           const float* __restrict__ w1, const float* __restrict__ b1,
                           const float* __restrict__ w2, const float* __restrict__ b2,
                           float* __restrict__ out)
{
    int b = blockIdx.x;
    int j = threadIdx.x;
    __shared__ float sh[64];
    float acc = __ldg(&b1[j]);
    const float* hv = hm + b * D_MODEL;
    const float* wv = w1 + j * D_MODEL;
    for (int k = 0; k < D_MODEL; k += 4) {
        float4 hh = *reinterpret_cast<const float4*>(&hv[k]);
        float4 ww = *reinterpret_cast<const float4*>(&wv[k]);
        acc = fmaf(hh.x, ww.x, acc);
        acc = fmaf(hh.y, ww.y, acc);
        acc = fmaf(hh.z, ww.z, acc);
        acc = fmaf(hh.w, ww.w, acc);
    }
    acc = fmaxf(acc, 0.f);
    sh[j] = acc * __ldg(&w2[j]);
    __syncthreads();
    if (j == 0) {
        float s = __ldg(&b2[0]);
        #pragma unroll
        for (int t = 0; t < 64; t++) s += sh[t];
        out[b] = s;
    }
}

// ---------------- launch ----------------
extern "C" void kernel_launch(void* const* d_in, const int* in_sizes, int n_in,
                              void* d_out, int out_size)
{
    const float* x          = (const float*)d_in[0];
    const float* proj_in_w  = (const float*)d_in[1];
    const float* proj_in_b  = (const float*)d_in[2];
    const float* in_proj_w  = (const float*)d_in[3];
    const float* conv_w     = (const float*)d_in[4];
    const float* conv_b     = (const float*)d_in[5];
    const float* x_proj_w   = (const float*)d_in[6];
    const float* dt_proj_w  = (const float*)d_in[7];
    const float* dt_proj_b  = (const float*)d_in[8];
    const float* A_log      = (const float*)d_in[9];
    const float* Dm         = (const float*)d_in[10];
    const float* out_proj_w = (const float*)d_in[11];
    const float* cls_w1     = (const float*)d_in[12];
    const float* cls_b1     = (const float*)d_in[13];
    const float* cls_w2     = (const float*)d_in[14];
    const float* cls_b2     = (const float*)d_in[15];

    void* p;
    cudaGetSymbolAddress(&p, g_ha);    float* ha    = (float*)p;
    cudaGetSymbolAddress(&p, g_hb);    float* hb    = (float*)p;
    cudaGetSymbolAddress(&p, g_xz);    float* xz    = (float*)p;
    cudaGetSymbolAddress(&p, g_xc);    float* xc    = (float*)p;
    cudaGetSymbolAddress(&p, g_xdbl);  float* xdbl  = (float*)p;
    cudaGetSymbolAddress(&p, g_xpart); float* xpart = (float*)p;
    cudaGetSymbolAddress(&p, g_dt);    float* dtb   = (float*)p;
    cudaGetSymbolAddress(&p, g_y);     float* y     = (float*)p;
    cudaGetSymbolAddress(&p, g_hpart); float* hpart = (float*)p;
    cudaGetSymbolAddress(&p, g_hm);    float* hm    = (float*)p;

    cudaFuncSetAttribute(gemm_mma, cudaFuncAttributeMaxDynamicSharedMemorySize, MMA_SMEM_BYTES);

    // h = x @ proj_in_w^T + b   (4096 x 512, K=128)  [mma]
    gemm_mma<<<dim3(D_MODEL / 128, ML / 128), 256, MMA_SMEM_BYTES>>>(
        x, D_IN, proj_in_w, D_IN, proj_in_b, ha, D_MODEL, D_IN);

    float* cur = ha;
    float* nxt = hb;
    for (int l = 0; l < N_LAYERS; l++) {
        const float* in_w  = in_proj_w  + (size_t)l * 2 * D_INNER * D_MODEL;
        const float* cw    = conv_w     + (size_t)l * D_INNER * D_CONV;
        const float* cb    = conv_b     + (size_t)l * D_INNER;
        const float* xp_w  = x_proj_w   + (size_t)l * 64 * D_INNER;
        const float* dt_w  = dt_proj_w  + (size_t)l * D_INNER * DT_RANK;
        const float* dt_b  = dt_proj_b  + (size_t)l * D_INNER;
        const float* Al    = A_log      + (size_t)l * D_INNER * D_STATE;
        const float* Dl    = Dm         + (size_t)l * D_INNER;
        const float* out_w = out_proj_w + (size_t)l * D_MODEL * D_INNER;

        // xz = h @ in_w^T   (4096 x 2048, K=512)  [mma]
        gemm_mma<<<dim3(2 * D_INNER / 128, ML / 128), 256, MMA_SMEM_BYTES>>>(
            cur, D_MODEL, in_w, D_MODEL, nullptr, xz, 2 * D_INNER, D_MODEL);
        // depthwise conv + silu
        conv_silu_kernel<<<(ML * D_INNER) / 256, 256>>>(xz, cw, cb, xc);
        // x_dbl = xc @ xp_w^T   (4096 x 64, K=1024) -- SIMT split-K
        gemm_nt<64><<<dim3(1, ML / GBM, KSPLIT), 256>>>(
            xc, D_INNER, xp_w, D_INNER, nullptr, xpart, ML, 64, D_INNER / KSPLIT, 0);
        reduce_ksplit<<<(ML * 64 + 255) / 256, 256>>>(xpart, xdbl, ML * 64);
        // dt = softplus(x_dbl[:, :32] @ dt_w^T + dt_b)  -- SIMT (K=32)
        gemm_nt<128><<<dim3(D_INNER / 128, ML / GBM), 256>>>(
            xdbl, 64, dt_w, DT_RANK, dt_b, dtb, ML, D_INNER, DT_RANK, 1);
        // selective scan + D skip + silu gate
        scan_kernel<<<dim3(D_INNER / 64, B_), 64>>>(dtb, xc, xdbl, xz, Al, Dl, y);
        // h = y @ out_w^T   (4096 x 512, K=1024)  [mma]
        gemm_mma<<<dim3(D_MODEL / 128, ML / 128), 256, MMA_SMEM_BYTES>>>(
            y, D_INNER, out_w, D_INNER, nullptr, nxt, D_MODEL, D_INNER);
        float* t = cur; cur = nxt; nxt = t;
    }

    mean_part_kernel<<<dim3(B_, 8), D_MODEL>>>(cur, hpart);
    mean_fin_kernel<<<(B_ * D_MODEL + 255) / 256, 256>>>(hpart, hm);
    cls_kernel<<<B_, 64>>>(hm, cls_w1, cls_b1, cls_w2, cls_b2, (float*)d_out);
}

// round 5
// speedup vs baseline: 4.1226x; 1.0421x over previous
#include <cuda_runtime.h>
#include <cuda_bf16.h>
#include <cstdint>

// ---------------- model dims ----------------
#define B_    8
#define L_    512
#define D_IN  128
#define D_MODEL 512
#define N_LAYERS 2
#define D_STATE 16
#define D_CONV  4
#define D_INNER 1024
#define DT_RANK 32
#define ML (B_ * L_)
#define KSPLIT 8

// ---------------- scratch ----------------
__device__ float g_ha[ML * D_MODEL];                 // final-layer h (fp32, for mean)
__device__ float g_xz[ML * 2 * D_INNER];
__device__ float g_xc[ML * D_INNER];
__device__ float g_xdbl[ML * 64];
__device__ float g_xpart[KSPLIT * ML * 64];
__device__ float g_dt[ML * D_INNER];
__device__ float g_hpart[B_ * 8 * D_MODEL];
__device__ float g_hm[B_ * D_MODEL];

// bf16 hi/lo planes
__device__ __align__(16) __nv_bfloat16 g_xh[ML * D_IN];
__device__ __align__(16) __nv_bfloat16 g_xl[ML * D_IN];
__device__ __align__(16) __nv_bfloat16 g_piwh[D_MODEL * D_IN];
__device__ __align__(16) __nv_bfloat16 g_piwl[D_MODEL * D_IN];
__device__ __align__(16) __nv_bfloat16 g_inwh[N_LAYERS * 2 * D_INNER * D_MODEL];
__device__ __align__(16) __nv_bfloat16 g_inwl[N_LAYERS * 2 * D_INNER * D_MODEL];
__device__ __align__(16) __nv_bfloat16 g_outwh[N_LAYERS * D_MODEL * D_INNER];
__device__ __align__(16) __nv_bfloat16 g_outwl[N_LAYERS * D_MODEL * D_INNER];
__device__ __align__(16) __nv_bfloat16 g_hh[ML * D_MODEL];
__device__ __align__(16) __nv_bfloat16 g_hl[ML * D_MODEL];
__device__ __align__(16) __nv_bfloat16 g_yh[ML * D_INNER];
__device__ __align__(16) __nv_bfloat16 g_yl[ML * D_INNER];

__device__ __forceinline__ float act_silu(float v) { return v / (1.f + __expf(-v)); }
__device__ __forceinline__ float act_softplus(float v) { return (v > 20.f) ? v : log1pf(__expf(v)); }

// =====================================================================
// PTX helpers
// =====================================================================
__device__ __forceinline__ void ldsm_x4(uint32_t* r, uint32_t addr) {
    asm volatile("ldmatrix.sync.aligned.m8n8.x4.shared.b16 {%0,%1,%2,%3}, [%4];"
                 : "=r"(r[0]), "=r"(r[1]), "=r"(r[2]), "=r"(r[3]) : "r"(addr));
}
__device__ __forceinline__ void mma16816(float* c, const uint32_t* a, const uint32_t* b) {
    asm volatile(
        "mma.sync.aligned.m16n8k16.row.col.f32.bf16.bf16.f32 "
        "{%0,%1,%2,%3}, {%4,%5,%6,%7}, {%8,%9}, {%0,%1,%2,%3};"
        : "+f"(c[0]), "+f"(c[1]), "+f"(c[2]), "+f"(c[3])
        : "r"(a[0]), "r"(a[1]), "r"(a[2]), "r"(a[3]), "r"(b[0]), "r"(b[1]));
}
__device__ __forceinline__ void cp16(uint32_t dst, const void* src) {
    asm volatile("cp.async.cg.shared.global [%0], [%1], 16;" :: "r"(dst), "l"(src));
}
#define CP_COMMIT() asm volatile("cp.async.commit_group;" ::: "memory")
#define CP_WAIT(n)  asm volatile("cp.async.wait_group %0;" :: "n"(n) : "memory")

__device__ __forceinline__ uint32_t bf2_bits(__nv_bfloat162 v) {
    return *reinterpret_cast<const uint32_t*>(&v);
}

// ---------------- fp32 -> bf16 hi/lo split (standalone) ----------------
__global__ void cvt_split(const float* __restrict__ src,
                          __nv_bfloat16* __restrict__ h,
                          __nv_bfloat16* __restrict__ l, int n4)
{
    int i = blockIdx.x * blockDim.x + threadIdx.x;
    if (i >= n4) return;
    float4 v = reinterpret_cast<const float4*>(src)[i];
    __nv_bfloat162 h0 = __floats2bfloat162_rn(v.x, v.y);
    __nv_bfloat162 h1 = __floats2bfloat162_rn(v.z, v.w);
    __nv_bfloat162 l0 = __floats2bfloat162_rn(v.x - __bfloat162float(h0.x),
                                              v.y - __bfloat162float(h0.y));
    __nv_bfloat162 l1 = __floats2bfloat162_rn(v.z - __bfloat162float(h1.x),
                                              v.w - __bfloat162float(h1.y));
    reinterpret_cast<uint2*>(h)[i] = make_uint2(bf2_bits(h0), bf2_bits(h1));
    reinterpret_cast<uint2*>(l)[i] = make_uint2(bf2_bits(l0), bf2_bits(l1));
}

// =====================================================================
// Tensor-core GEMM (mma.sync, bf16 hi/lo planes, cp.async double-buffer)
// C[M,N] = A*W^T (+bias). CTA 128x128, warp 64x32, K-chunk 64.
// Optional outputs: fp32 C, and/or bf16 hi/lo planes (Ch, Cl).
// smem: 2 x 64KB buffers, each: Ah(16K) Al(16K) Wh(16K) Wl(16K), SW128.
// =====================================================================
#define MMA_SMEM_BYTES 131072

__global__ __launch_bounds__(256) void gemm_mma(
    const __nv_bfloat16* __restrict__ Ah, const __nv_bfloat16* __restrict__ Al, int lda,
    const __nv_bfloat16* __restrict__ Wh, const __nv_bfloat16* __restrict__ Wl, int ldw,
    const float* __restrict__ bias, float* __restrict__ C,
    __nv_bfloat16* __restrict__ Ch, __nv_bfloat16* __restrict__ Cl,
    int N, int K)
{
    extern __shared__ char smem[];
    const uint32_t sbase = (uint32_t)__cvta_generic_to_shared(smem);
    const int tid = threadIdx.x;
    const int lane = tid & 31;
    const int wid = tid >> 5;
    const int wm = wid >> 2;
    const int wn = wid & 3;
    const int bm = blockIdx.y * 128;
    const int bn = blockIdx.x * 128;

    // ---- cp.async fill coords
    const int r_base = tid >> 3;           // 0..31
    const int s = tid & 7;                 // 16B segment
    const uint32_t sw_base =
        (uint32_t)(r_base * 128 + s * 16) ^ (((uint32_t)r_base & 7u) << 4);
    const size_t aoff = (size_t)(bm + r_base) * lda + s * 8;
    const size_t woff = (size_t)(bn + r_base) * ldw + s * 8;

    auto fill = [&](int buf, int k0) {
        const uint32_t bb = sbase + (uint32_t)buf * 65536;
        #pragma unroll
        for (int u = 0; u < 16; u++) {
            const int plane = u >> 2;
            const size_t roff = (size_t)((u & 3) * 32);
            const uint32_t dst = bb + (uint32_t)plane * 16384 + (uint32_t)((u & 3) * 4096) + sw_base;
            const __nv_bfloat16* g;
            if (plane == 0)      g = Ah + aoff + roff * lda + k0;
            else if (plane == 1) g = Al + aoff + roff * lda + k0;
            else if (plane == 2) g = Wh + woff + roff * ldw + k0;
            else                 g = Wl + woff + roff * ldw + k0;
            cp16(dst, g);
        }
    };

    // ---- fragment lane addressing (SW128: xor = (row&7)<<4)
    const int l7 = lane & 7;
    const uint32_t xorv = (uint32_t)l7 << 4;
    const int a_row = wm * 64 + l7 + ((lane >> 3) & 1) * 8;
    const uint32_t a_kb = (uint32_t)((lane >> 4) & 1) * 16;
    const int b_row = wn * 32 + ((lane >> 4) & 1) * 8 + l7;
    const uint32_t b_kb = (uint32_t)((lane >> 3) & 1) * 16;

    float acc[4][4][4];
    #pragma unroll
    for (int i = 0; i < 4; i++)
        #pragma unroll
        for (int j = 0; j < 4; j++)
            #pragma unroll
            for (int r = 0; r < 4; r++) acc[i][j][r] = 0.f;

    const int nt = K / 64;

    fill(0, 0);
    CP_COMMIT();

    for (int t = 0; t < nt; t++) {
        const int buf = t & 1;
        if (t + 1 < nt) {
            fill(buf ^ 1, (t + 1) * 64);
            CP_COMMIT();
            CP_WAIT(1);
        } else {
            CP_WAIT(0);
        }
        __syncthreads();

        const uint32_t bb = sbase + (uint32_t)buf * 65536;
        #pragma unroll
        for (int kk = 0; kk < 4; kk++) {
            const uint32_t koff_a = ((uint32_t)(kk * 32) + a_kb) ^ xorv;
            const uint32_t koff_b = ((uint32_t)(kk * 32) + b_kb) ^ xorv;
            uint32_t ah[4][4], al[4][4], bh[2][4], bl[2][4];
            #pragma unroll
            for (int i = 0; i < 4; i++) {
                uint32_t ad = bb + (uint32_t)((a_row + i * 16) * 128) + koff_a;
                ldsm_x4(ah[i], ad);
                ldsm_x4(al[i], ad + 16384);
            }
            #pragma unroll
            for (int jj = 0; jj < 2; jj++) {
                uint32_t bd = bb + 32768 + (uint32_t)((b_row + jj * 16) * 128) + koff_b;
                ldsm_x4(bh[jj], bd);
                ldsm_x4(bl[jj], bd + 16384);
            }
            #pragma unroll
            for (int i = 0; i < 4; i++) {
                #pragma unroll
                for (int j = 0; j < 4; j++) {
                    const uint32_t* bhp = &bh[j >> 1][(j & 1) * 2];
                    const uint32_t* blp = &bl[j >> 1][(j & 1) * 2];
                    mma16816(acc[i][j], ah[i], bhp);
                    mma16816(acc[i][j], ah[i], blp);
                    mma16816(acc[i][j], al[i], bhp);
                }
            }
        }
        __syncthreads();
    }

    // ---- epilogue
    const int g = lane >> 2;
    const int t4 = lane & 3;
    #pragma unroll
    for (int i = 0; i < 4; i++) {
        const int r0 = bm + wm * 64 + i * 16 + g;
        const int r1 = r0 + 8;
        #pragma unroll
        for (int j = 0; j < 4; j++) {
            const int col = bn + wn * 32 + j * 8 + t4 * 2;
            const float b0 = bias ? __ldg(&bias[col]) : 0.f;
            const float b1 = bias ? __ldg(&bias[col + 1]) : 0.f;
            float2 v0 = make_float2(acc[i][j][0] + b0, acc[i][j][1] + b1);
            float2 v1 = make_float2(acc[i][j][2] + b0, acc[i][j][3] + b1);
            if (C) {
                *reinterpret_cast<float2*>(&C[(size_t)r0 * N + col]) = v0;
                *reinterpret_cast<float2*>(&C[(size_t)r1 * N + col]) = v1;
            }
            if (Ch) {
                __nv_bfloat162 h0 = __floats2bfloat162_rn(v0.x, v0.y);
                __nv_bfloat162 h1 = __floats2bfloat162_rn(v1.x, v1.y);
                __nv_bfloat162 l0 = __floats2bfloat162_rn(v0.x - __bfloat162float(h0.x),
                                                          v0.y - __bfloat162float(h0.y));
                __nv_bfloat162 l1 = __floats2bfloat162_rn(v1.x - __bfloat162float(h1.x),
                                                          v1.y - __bfloat162float(h1.y));
                *reinterpret_cast<uint32_t*>(&Ch[(size_t)r0 * N + col]) = bf2_bits(h0);
                *reinterpret_cast<uint32_t*>(&Ch[(size_t)r1 * N + col]) = bf2_bits(h1);
                *reinterpret_cast<uint32_t*>(&Cl[(size_t)r0 * N + col]) = bf2_bits(l0);
                *reinterpret_cast<uint32_t*>(&Cl[(size_t)r1 * N + col]) = bf2_bits(l1);
            }
        }
    }
}

// =====================================================================
// SIMT GEMM (x_proj split-K, dt_proj)
// =====================================================================
#define GBM 128
#define GBK 16

template<int BN>
__global__ __launch_bounds__(256) void gemm_nt(
    const float* __restrict__ A, int lda,
    const float* __restrict__ W, int ldw,
    const float* __restrict__ bias, float* __restrict__ C,
    int M, int N, int K, int act)
{
    constexpr int TN = BN / 16;
    constexpr int WU = (BN * 4) / 256;

    __shared__ float As[2][GBK][GBM];
    __shared__ float Ws[2][GBK][BN];

    const int z = blockIdx.z;
    A += (size_t)z * K;
    W += (size_t)z * K;
    C += (size_t)z * M * N;

    const int bm = blockIdx.y * GBM;
    const int bn = blockIdx.x * BN;
    const int tid = threadIdx.x;
    const int tr = tid >> 4;
    const int tc = tid & 15;

    float acc[8][TN];
    #pragma unroll
    for (int i = 0; i < 8; i++)
        #pragma unroll
        for (int j = 0; j < TN; j++) acc[i][j] = 0.f;

    float4 ra[2], rw[WU];
    int ai[2], aj[2], wi[WU], wj[WU];
    #pragma unroll
    for (int u = 0; u < 2; u++) { int s = tid + u * 256; ai[u] = s >> 2; aj[u] = (s & 3) << 2; }
    #pragma unroll
    for (int u = 0; u < WU; u++) { int s = tid + u * 256; wi[u] = s >> 2; wj[u] = (s & 3) << 2; }

    const int nt = K / GBK;

    #pragma unroll
    for (int u = 0; u < 2; u++)
        ra[u] = *reinterpret_cast<const float4*>(&A[(size_t)(bm + ai[u]) * lda + aj[u]]);
    #pragma unroll
    for (int u = 0; u < WU; u++)
        rw[u] = *reinterpret_cast<const float4*>(&W[(size_t)(bn + wi[u]) * ldw + wj[u]]);
    #pragma unroll
    for (int u = 0; u < 2; u++) {
        As[0][aj[u] + 0][ai[u]] = ra[u].x; As[0][aj[u] + 1][ai[u]] = ra[u].y;
        As[0][aj[u] + 2][ai[u]] = ra[u].z; As[0][aj[u] + 3][ai[u]] = ra[u].w;
    }
    #pragma unroll
    for (int u = 0; u < WU; u++) {
        Ws[0][wj[u] + 0][wi[u]] = rw[u].x; Ws[0][wj[u] + 1][wi[u]] = rw[u].y;
        Ws[0][wj[u] + 2][wi[u]] = rw[u].z; Ws[0][wj[u] + 3][wi[u]] = rw[u].w;
    }
    __syncthreads();

    for (int t = 0; t < nt; t++) {
        const int buf = t & 1;
        const bool more = (t + 1 < nt);
        if (more) {
            const int k0 = (t + 1) * GBK;
            #pragma unroll
            for (int u = 0; u < 2; u++)
                ra[u] = *reinterpret_cast<const float4*>(&A[(size_t)(bm + ai[u]) * lda + k0 + aj[u]]);
            #pragma unroll
            for (int u = 0; u < WU; u++)
                rw[u] = *reinterpret_cast<const float4*>(&W[(size_t)(bn + wi[u]) * ldw + k0 + wj[u]]);
        }

        #pragma unroll
        for (int k = 0; k < GBK; k++) {
            float a[8], w[TN];
            float4 a0 = *reinterpret_cast<const float4*>(&As[buf][k][tr * 8]);
            float4 a1 = *reinterpret_cast<const float4*>(&As[buf][k][tr * 8 + 4]);
            a[0]=a0.x; a[1]=a0.y; a[2]=a0.z; a[3]=a0.w;
            a[4]=a1.x; a[5]=a1.y; a[6]=a1.z; a[7]=a1.w;
            #pragma unroll
            for (int j4 = 0; j4 < TN; j4 += 4) {
                float4 w0 = *reinterpret_cast<const float4*>(&Ws[buf][k][tc * TN + j4]);
                w[j4+0]=w0.x; w[j4+1]=w0.y; w[j4+2]=w0.z; w[j4+3]=w0.w;
            }
            #pragma unroll
            for (int i = 0; i < 8; i++)
                #pragma unroll
                for (int j = 0; j < TN; j++)
                    acc[i][j] = fmaf(a[i], w[j], acc[i][j]);
        }

        if (more) {
            const int nbuf = buf ^ 1;
            #pragma unroll
            for (int u = 0; u < 2; u++) {
                As[nbuf][aj[u] + 0][ai[u]] = ra[u].x; As[nbuf][aj[u] + 1][ai[u]] = ra[u].y;
                As[nbuf][aj[u] + 2][ai[u]] = ra[u].z; As[nbuf][aj[u] + 3][ai[u]] = ra[u].w;
            }
            #pragma unroll
            for (int u = 0; u < WU; u++) {
                Ws[nbuf][wj[u] + 0][wi[u]] = rw[u].x; Ws[nbuf][wj[u] + 1][wi[u]] = rw[u].y;
                Ws[nbuf][wj[u] + 2][wi[u]] = rw[u].z; Ws[nbuf][wj[u] + 3][wi[u]] = rw[u].w;
            }
        }
        __syncthreads();
    }

    float bfrag[TN];
    #pragma unroll
    for (int j = 0; j < TN; j++)
        bfrag[j] = bias ? __ldg(&bias[bn + tc * TN + j]) : 0.f;

    #pragma unroll
    for (int i = 0; i < 8; i++) {
        const size_t row = bm + tr * 8 + i;
        #pragma unroll
        for (int j4 = 0; j4 < TN; j4 += 4) {
            float4 v;
            float* vv = &v.x;
            #pragma unroll
            for (int j = 0; j < 4; j++) {
                float u = acc[i][j4 + j] + bfrag[j4 + j];
                if (act == 1) u = act_softplus(u);
                vv[j] = u;
            }
            *reinterpret_cast<float4*>(&C[row * N + bn + tc * TN + j4]) = v;
        }
    }
}

__global__ void reduce_ksplit(const float* __restrict__ part, float* __restrict__ out, int n)
{
    int i = blockIdx.x * blockDim.x + threadIdx.x;
    if (i >= n) return;
    float acc = 0.f;
    #pragma unroll
    for (int zz = 0; zz < KSPLIT; zz++) acc += part[(size_t)zz * n + i];
    out[i] = acc;
}

// ---------------- causal depthwise conv1d + bias + SiLU ----------------
__global__ void conv_silu_kernel(const float* __restrict__ xz,
                                 const float* __restrict__ cw,
                                 const float* __restrict__ cb,
                                 float* __restrict__ xc)
{
    int idx = blockIdx.x * blockDim.x + threadIdx.x;
    if (idx >= ML * D_INNER) return;
    int d = idx & (D_INNER - 1);
    int bl = idx >> 10;
    int l = bl & (L_ - 1);
    int b = bl >> 9;

    float w0 = __ldg(&cw[d * 4 + 0]);
    float w1 = __ldg(&cw[d * 4 + 1]);
    float w2 = __ldg(&cw[d * 4 + 2]);
    float w3 = __ldg(&cw[d * 4 + 3]);
    float acc = __ldg(&cb[d]);

    const size_t rowstride = 2 * D_INNER;
    size_t base = ((size_t)b * L_) * rowstride + d;
    if (l >= 3) acc = fmaf(w0, xz[base + (size_t)(l - 3) * rowstride], acc);
    if (l >= 2) acc = fmaf(w1, xz[base + (size_t)(l - 2) * rowstride], acc);
    if (l >= 1) acc = fmaf(w2, xz[base + (size_t)(l - 1) * rowstride], acc);
    acc = fmaf(w3, xz[base + (size_t)l * rowstride], acc);

    xc[idx] = act_silu(acc);
}

// ---------------- selective scan (emits y as bf16 hi/lo planes) ----------------
__global__ __launch_bounds__(64) void scan_kernel(
    const float* __restrict__ dt, const float* __restrict__ xc,
    const float* __restrict__ xdbl, const float* __restrict__ xz,
    const float* __restrict__ A_log, const float* __restrict__ Dm,
    __nv_bfloat16* __restrict__ yh, __nv_bfloat16* __restrict__ yl)
{
    const int tid = threadIdx.x;
    const int d = blockIdx.x * 64 + tid;
    const int b = blockIdx.y;

    __shared__ float sBC[2][8][32];

    float Av[D_STATE];
    #pragma unroll
    for (int s = 0; s < D_STATE; s++) Av[s] = -__expf(__ldg(&A_log[d * D_STATE + s]));
    const float Av0 = Av[0];
    int fastl = 1;
    #pragma unroll
    for (int s = 1; s < D_STATE; s++) {
        float tgt = (s + 1) * Av0;
        fastl &= (fabsf(Av[s] - tgt) <= 1e-4f * fabsf(tgt)) ? 1 : 0;
    }
    const int fast = __syncthreads_and(fastl);

    float h[D_STATE];
    #pragma unroll
    for (int s = 0; s < D_STATE; s++) h[s] = 0.f;
    const float Dd = __ldg(&Dm[d]);
    const size_t rowb = (size_t)b * L_;

    float cdt[8], cxc[8], cz[8], ndt[8], nxc[8], nz[8];

    {
        int r = tid >> 3, q = tid & 7;
        float4 v = *reinterpret_cast<const float4*>(&xdbl[(rowb + r) * 64 + 32 + q * 4]);
        *reinterpret_cast<float4*>(&sBC[0][r][q * 4]) = v;
    }
    #pragma unroll
    for (int i = 0; i < 8; i++) {
        size_t row = rowb + i;
        cdt[i] = __ldg(&dt[row * D_INNER + d]);
        cxc[i] = __ldg(&xc[row * D_INNER + d]);
        cz[i]  = __ldg(&xz[row * 2 * D_INNER + D_INNER + d]);
    }
    __syncthreads();

    for (int w = 0; w < L_ / 8; w++) {
        const int slot = w & 1;
        if (w + 1 < L_ / 8) {
            int r = tid >> 3, q = tid & 7;
            float4 v = *reinterpret_cast<const float4*>(
                &xdbl[(rowb + (w + 1) * 8 + r) * 64 + 32 + q * 4]);
            *reinterpret_cast<float4*>(&sBC[slot ^ 1][r][q * 4]) = v;
            #pragma unroll
            for (int i = 0; i < 8; i++) {
                size_t row = rowb + (w + 1) * 8 + i;
                ndt[i] = __ldg(&dt[row * D_INNER + d]);
                nxc[i] = __ldg(&xc[row * D_INNER + d]);
                nz[i]  = __ldg(&xz[row * 2 * D_INNER + D_INNER + d]);
            }
        }

        #pragma unroll
        for (int i = 0; i < 8; i++) {
            const float dtv = cdt[i], xv = cxc[i], zv = cz[i];
            const float p = dtv * xv;
            const float* bc = sBC[slot][i];
            float acc0 = 0.f, acc1 = 0.f;
            if (fast) {
                const float q1 = __expf(dtv * Av0);
                const float q2 = q1 * q1, q3 = q2 * q1, q4 = q2 * q2;
                const float q5 = q4 * q1, q6 = q4 * q2, q7 = q4 * q3, q8 = q4 * q4;
                const float dA[16] = {q1, q2, q3, q4, q5, q6, q7, q8,
                                      q8*q1, q8*q2, q8*q3, q8*q4, q8*q5, q8*q6, q8*q7, q8*q8};
                #pragma unroll
                for (int s = 0; s < D_STATE; s++) {
                    float hs = fmaf(dA[s], h[s], p * bc[s]);
                    h[s] = hs;
                    if (s & 1) acc1 = fmaf(hs, bc[16 + s], acc1);
                    else       acc0 = fmaf(hs, bc[16 + s], acc0);
                }
            } else {
                #pragma unroll
                for (int s = 0; s < D_STATE; s++) {
                    float hs = fmaf(__expf(dtv * Av[s]), h[s], p * bc[s]);
                    h[s] = hs;
                    if (s & 1) acc1 = fmaf(hs, bc[16 + s], acc1);
                    else       acc0 = fmaf(hs, bc[16 + s], acc0);
                }
            }
            const size_t row = rowb + w * 8 + i;
            float yv = fmaf(xv, Dd, acc0 + acc1) * act_silu(zv);
            __nv_bfloat16 hh = __float2bfloat16(yv);
            yh[row * D_INNER + d] = hh;
            yl[row * D_INNER + d] = __float2bfloat16(yv - __bfloat162float(hh));
        }

        #pragma unroll
        for (int i = 0; i < 8; i++) { cdt[i] = ndt[i]; cxc[i] = nxc[i]; cz[i] = nz[i]; }
        __syncthreads();
    }
}

// ---------------- mean over L (2-stage) ----------------
__global__ void mean_part_kernel(const float* __restrict__ h, float* __restrict__ part)
{
    int b = blockIdx.x, lc = blockIdx.y, d = threadIdx.x;
    float acc = 0.f;
    #pragma unroll 8
    for (int l = lc * 64; l < lc * 64 + 64; l++)
        acc += h[((size_t)b * L_ + l) * D_MODEL + d];
    part[(b * 8 + lc) * D_MODEL + d] = acc;
}
__global__ void mean_fin_kernel(const float* __restrict__ part, float* __restrict__ hm)
{
    int i = blockIdx.x * blockDim.x + threadIdx.x;
    if (i >= B_ * D_MODEL) return;
    int b = i / D_MODEL, d = i % D_MODEL;
    float acc = 0.f;
    #pragma unroll
    for (int c = 0; c < 8; c++) acc += part[(b * 8 + c) * D_MODEL + d];
    hm[i] = acc * (1.f / L_);
}

// ---------------- classifier head ----------------
__global__ void cls_kernel(const float* __restrict__ hm,
                           const float* __restrict__ w1, const float* __restrict__ b1,
                           const float* __restrict__ w2, const float* __restrict__ b2,
                           float* __restrict__ out)
{
    int b = blockIdx.x;
    int j = threadIdx.x;
    __shared__ float sh[64];
    float acc = __ldg(&b1[j]);
    const float* hv = hm + b * D_MODEL;
    const float* wv = w1 + j * D_MODEL;
    for (int k = 0; k < D_MODEL; k += 4) {
        float4 hh = *reinterpret_cast<const float4*>(&hv[k]);
        float4 ww = *reinterpret_cast<const float4*>(&wv[k]);
        acc = fmaf(hh.x, ww.x, acc);
        acc = fmaf(hh.y, ww.y, acc);
        acc = fmaf(hh.z, ww.z, acc);
        acc = fmaf(hh.w, ww.w, acc);
    }
    acc = fmaxf(acc, 0.f);
    sh[j] = acc * __ldg(&w2[j]);
    __syncthreads();
    if (j == 0) {
        float s = __ldg(&b2[0]);
        #pragma unroll
        for (int t = 0; t < 64; t++) s += sh[t];
        out[b] = s;
    }
}

// ---------------- launch ----------------
extern "C" void kernel_launch(void* const* d_in, const int* in_sizes, int n_in,
                              void* d_out, int out_size)
{
    const float* x          = (const float*)d_in[0];
    const float* proj_in_w  = (const float*)d_in[1];
    const float* proj_in_b  = (const float*)d_in[2];
    const float* in_proj_w  = (const float*)d_in[3];
    const float* conv_w     = (const float*)d_in[4];
    const float* conv_b     = (const float*)d_in[5];
    const float* x_proj_w   = (const float*)d_in[6];
    const float* dt_proj_w  = (const float*)d_in[7];
    const float* dt_proj_b  = (const float*)d_in[8];
    const float* A_log      = (const float*)d_in[9];
    const float* Dm         = (const float*)d_in[10];
    const float* out_proj_w = (const float*)d_in[11];
    const float* cls_w1     = (const float*)d_in[12];
    const float* cls_b1     = (const float*)d_in[13];
    const float* cls_w2     = (const float*)d_in[14];
    const float* cls_b2     = (const float*)d_in[15];

    void* p;
    cudaGetSymbolAddress(&p, g_ha);    float* ha    = (float*)p;
    cudaGetSymbolAddress(&p, g_xz);    float* xz    = (float*)p;
    cudaGetSymbolAddress(&p, g_xc);    float* xc    = (float*)p;
    cudaGetSymbolAddress(&p, g_xdbl);  float* xdbl  = (float*)p;
    cudaGetSymbolAddress(&p, g_xpart); float* xpart = (float*)p;
    cudaGetSymbolAddress(&p, g_dt);    float* dtb   = (float*)p;
    cudaGetSymbolAddress(&p, g_hpart); float* hpart = (float*)p;
    cudaGetSymbolAddress(&p, g_hm);    float* hm    = (float*)p;

    __nv_bfloat16 *xh, *xl, *piwh, *piwl, *inwh, *inwl, *outwh, *outwl, *hh, *hl, *yh, *yl;
    cudaGetSymbolAddress(&p, g_xh);    xh    = (__nv_bfloat16*)p;
    cudaGetSymbolAddress(&p, g_xl);    xl    = (__nv_bfloat16*)p;
    cudaGetSymbolAddress(&p, g_piwh);  piwh  = (__nv_bfloat16*)p;
    cudaGetSymbolAddress(&p, g_piwl);  piwl  = (__nv_bfloat16*)p;
    cudaGetSymbolAddress(&p, g_inwh);  inwh  = (__nv_bfloat16*)p;
    cudaGetSymbolAddress(&p, g_inwl);  inwl  = (__nv_bfloat16*)p;
    cudaGetSymbolAddress(&p, g_outwh); outwh = (__nv_bfloat16*)p;
    cudaGetSymbolAddress(&p, g_outwl); outwl = (__nv_bfloat16*)p;
    cudaGetSymbolAddress(&p, g_hh);    hh    = (__nv_bfloat16*)p;
    cudaGetSymbolAddress(&p, g_hl);    hl    = (__nv_bfloat16*)p;
    cudaGetSymbolAddress(&p, g_yh);    yh    = (__nv_bfloat16*)p;
    cudaGetSymbolAddress(&p, g_yl);    yl    = (__nv_bfloat16*)p;

    cudaFuncSetAttribute(gemm_mma, cudaFuncAttributeMaxDynamicSharedMemorySize, MMA_SMEM_BYTES);

    // ---- pre-split inputs/weights to bf16 hi/lo planes
    cvt_split<<<(ML * D_IN / 4 + 255) / 256, 256>>>(x, xh, xl, ML * D_IN / 4);
    cvt_split<<<(D_MODEL * D_IN / 4 + 255) / 256, 256>>>(proj_in_w, piwh, piwl, D_MODEL * D_IN / 4);
    cvt_split<<<(N_LAYERS * 2 * D_INNER * D_MODEL / 4 + 255) / 256, 256>>>(
        in_proj_w, inwh, inwl, N_LAYERS * 2 * D_INNER * D_MODEL / 4);
    cvt_split<<<(N_LAYERS * D_MODEL * D_INNER / 4 + 255) / 256, 256>>>(
        out_proj_w, outwh, outwl, N_LAYERS * D_MODEL * D_INNER / 4);

    // h = x @ proj_in_w^T + b  -> emit h planes only
    gemm_mma<<<dim3(D_MODEL / 128, ML / 128), 256, MMA_SMEM_BYTES>>>(
        xh, xl, D_IN, piwh, piwl, D_IN, proj_in_b, nullptr, hh, hl, D_MODEL, D_IN);

    for (int l = 0; l < N_LAYERS; l++) {
        const size_t inw_off  = (size_t)l * 2 * D_INNER * D_MODEL;
        const size_t outw_off = (size_t)l * D_MODEL * D_INNER;
        const float* cw    = conv_w     + (size_t)l * D_INNER * D_CONV;
        const float* cb    = conv_b     + (size_t)l * D_INNER;
        const float* xp_w  = x_proj_w   + (size_t)l * 64 * D_INNER;
        const float* dt_w  = dt_proj_w  + (size_t)l * D_INNER * DT_RANK;
        const float* dt_b  = dt_proj_b  + (size_t)l * D_INNER;
        const float* Al    = A_log      + (size_t)l * D_INNER * D_STATE;
        const float* Dl    = Dm         + (size_t)l * D_INNER;
        const bool last = (l == N_LAYERS - 1);

        // xz = h @ in_w^T   (fp32 out; consumed by conv + scan)
        gemm_mma<<<dim3(2 * D_INNER / 128, ML / 128), 256, MMA_SMEM_BYTES>>>(
            hh, hl, D_MODEL, inwh + inw_off, inwl + inw_off, D_MODEL,
            nullptr, xz, nullptr, nullptr, 2 * D_INNER, D_MODEL);
        // depthwise conv + silu
        conv_silu_kernel<<<(ML * D_INNER) / 256, 256>>>(xz, cw, cb, xc);
        // x_dbl = xc @ xp_w^T  (SIMT split-K)
        gemm_nt<64><<<dim3(1, ML / GBM, KSPLIT), 256>>>(
            xc, D_INNER, xp_w, D_INNER, nullptr, xpart, ML, 64, D_INNER / KSPLIT, 0);
        reduce_ksplit<<<(ML * 64 + 255) / 256, 256>>>(xpart, xdbl, ML * 64);
        // dt = softplus(x_dbl[:, :32] @ dt_w^T + dt_b)  (SIMT, K=32)
        gemm_nt<128><<<dim3(D_INNER / 128, ML / GBM), 256>>>(
            xdbl, 64, dt_w, DT_RANK, dt_b, dtb, ML, D_INNER, DT_RANK, 1);
        // selective scan -> y planes
        scan_kernel<<<dim3(D_INNER / 64, B_), 64>>>(dtb, xc, xdbl, xz, Al, Dl, yh, yl);
        // h = y @ out_w^T : mid layers -> planes; last layer -> fp32 for mean
        gemm_mma<<<dim3(D_MODEL / 128, ML / 128), 256, MMA_SMEM_BYTES>>>(
            yh, yl, D_INNER, outwh + outw_off, outwl + outw_off, D_INNER,
            nullptr, last ? ha : nullptr, last ? nullptr : hh, last ? nullptr : hl,
            D_MODEL, D_INNER);
    }

    mean_part_kernel<<<dim3(B_, 8), D_MODEL>>>(ha, hpart);
    mean_fin_kernel<<<(B_ * D_MODEL + 255) / 256, 256>>>(hpart, hm);
    cls_kernel<<<B_, 64>>>(hm, cls_w1, cls_b1, cls_w2, cls_b2, (float*)d_out);
}

// round 6
// speedup vs baseline: 4.1820x; 1.0144x over previous
#include <cuda_runtime.h>
#include <cuda_bf16.h>
#include <cstdint>

// ---------------- model dims ----------------
#define B_    8
#define L_    512
#define D_IN  128
#define D_MODEL 512
#define N_LAYERS 2
#define D_STATE 16
#define D_CONV  4
#define D_INNER 1024
#define DT_RANK 32
#define ML (B_ * L_)
#define KSPLIT 8

// ---------------- scratch ----------------
__device__ float g_ha[ML * D_MODEL];
__device__ float g_xz[ML * 2 * D_INNER];
__device__ float g_xc[ML * D_INNER];
__device__ float g_xdbl[ML * 64];
__device__ float g_xpart[KSPLIT * ML * 64];
__device__ float g_dt[ML * D_INNER];
__device__ float g_hpart[B_ * 8 * D_MODEL];
__device__ float g_hm[B_ * D_MODEL];

// bf16 hi/lo planes
__device__ __align__(16) __nv_bfloat16 g_xh[ML * D_IN];
__device__ __align__(16) __nv_bfloat16 g_xl[ML * D_IN];
__device__ __align__(16) __nv_bfloat16 g_piwh[D_MODEL * D_IN];
__device__ __align__(16) __nv_bfloat16 g_piwl[D_MODEL * D_IN];
__device__ __align__(16) __nv_bfloat16 g_inwh[N_LAYERS * 2 * D_INNER * D_MODEL];
__device__ __align__(16) __nv_bfloat16 g_inwl[N_LAYERS * 2 * D_INNER * D_MODEL];
__device__ __align__(16) __nv_bfloat16 g_outwh[N_LAYERS * D_MODEL * D_INNER];
__device__ __align__(16) __nv_bfloat16 g_outwl[N_LAYERS * D_MODEL * D_INNER];
__device__ __align__(16) __nv_bfloat16 g_hh[ML * D_MODEL];
__device__ __align__(16) __nv_bfloat16 g_hl[ML * D_MODEL];
__device__ __align__(16) __nv_bfloat16 g_yh[ML * D_INNER];
__device__ __align__(16) __nv_bfloat16 g_yl[ML * D_INNER];

__device__ __forceinline__ float act_silu(float v) { return v / (1.f + __expf(-v)); }
__device__ __forceinline__ float act_softplus(float v) { return (v > 20.f) ? v : log1pf(__expf(v)); }

// =====================================================================
// PTX helpers
// =====================================================================
__device__ __forceinline__ void ldsm_x4(uint32_t* r, uint32_t addr) {
    asm volatile("ldmatrix.sync.aligned.m8n8.x4.shared.b16 {%0,%1,%2,%3}, [%4];"
                 : "=r"(r[0]), "=r"(r[1]), "=r"(r[2]), "=r"(r[3]) : "r"(addr));
}
__device__ __forceinline__ void mma16816(float* c, const uint32_t* a, const uint32_t* b) {
    asm volatile(
        "mma.sync.aligned.m16n8k16.row.col.f32.bf16.bf16.f32 "
        "{%0,%1,%2,%3}, {%4,%5,%6,%7}, {%8,%9}, {%0,%1,%2,%3};"
        : "+f"(c[0]), "+f"(c[1]), "+f"(c[2]), "+f"(c[3])
        : "r"(a[0]), "r"(a[1]), "r"(a[2]), "r"(a[3]), "r"(b[0]), "r"(b[1]));
}
__device__ __forceinline__ void cp16(uint32_t dst, const void* src) {
    asm volatile("cp.async.cg.shared.global [%0], [%1], 16;" :: "r"(dst), "l"(src));
}
#define CP_COMMIT() asm volatile("cp.async.commit_group;" ::: "memory")
#define CP_WAIT(n)  asm volatile("cp.async.wait_group %0;" :: "n"(n) : "memory")

__device__ __forceinline__ uint32_t bf2_bits(__nv_bfloat162 v) {
    return *reinterpret_cast<const uint32_t*>(&v);
}

// ---------------- fp32 -> bf16 hi/lo split (two tensors per launch) ----------------
__global__ void cvt_split2(const float* __restrict__ s0,
                           __nv_bfloat16* __restrict__ h0, __nv_bfloat16* __restrict__ l0, int n0,
                           const float* __restrict__ s1,
                           __nv_bfloat16* __restrict__ h1, __nv_bfloat16* __restrict__ l1, int n1)
{
    int i = blockIdx.x * blockDim.x + threadIdx.x;
    const float* src; __nv_bfloat16 *h, *l;
    if (i < n0) { src = s0; h = h0; l = l0; }
    else {
        i -= n0;
        if (i >= n1) return;
        src = s1; h = h1; l = l1;
    }
    float4 v = reinterpret_cast<const float4*>(src)[i];
    __nv_bfloat162 hh0 = __floats2bfloat162_rn(v.x, v.y);
    __nv_bfloat162 hh1 = __floats2bfloat162_rn(v.z, v.w);
    __nv_bfloat162 ll0 = __floats2bfloat162_rn(v.x - __bfloat162float(hh0.x),
                                               v.y - __bfloat162float(hh0.y));
    __nv_bfloat162 ll1 = __floats2bfloat162_rn(v.z - __bfloat162float(hh1.x),
                                               v.w - __bfloat162float(hh1.y));
    reinterpret_cast<uint2*>(h)[i] = make_uint2(bf2_bits(hh0), bf2_bits(hh1));
    reinterpret_cast<uint2*>(l)[i] = make_uint2(bf2_bits(ll0), bf2_bits(ll1));
}

// =====================================================================
// Tensor-core GEMM (mma.sync, bf16 hi/lo planes, cp.async double-buffer)
// Term-major MMA issue order: 16 independent MMAs between reuse of any
// accumulator (no back-to-back dependent HMMA on same acc).
// =====================================================================
#define MMA_SMEM_BYTES 131072

__global__ __launch_bounds__(256, 1) void gemm_mma(
    const __nv_bfloat16* __restrict__ Ah, const __nv_bfloat16* __restrict__ Al, int lda,
    const __nv_bfloat16* __restrict__ Wh, const __nv_bfloat16* __restrict__ Wl, int ldw,
    const float* __restrict__ bias, float* __restrict__ C,
    __nv_bfloat16* __restrict__ Ch, __nv_bfloat16* __restrict__ Cl,
    int N, int K)
{
    extern __shared__ char smem[];
    const uint32_t sbase = (uint32_t)__cvta_generic_to_shared(smem);
    const int tid = threadIdx.x;
    const int lane = tid & 31;
    const int wid = tid >> 5;
    const int wm = wid >> 2;
    const int wn = wid & 3;
    const int bm = blockIdx.y * 128;
    const int bn = blockIdx.x * 128;

    const int r_base = tid >> 3;
    const int s = tid & 7;
    const uint32_t sw_base =
        (uint32_t)(r_base * 128 + s * 16) ^ (((uint32_t)r_base & 7u) << 4);
    const size_t aoff = (size_t)(bm + r_base) * lda + s * 8;
    const size_t woff = (size_t)(bn + r_base) * ldw + s * 8;

    auto fill = [&](int buf, int k0) {
        const uint32_t bb = sbase + (uint32_t)buf * 65536;
        #pragma unroll
        for (int u = 0; u < 16; u++) {
            const int plane = u >> 2;
            const size_t roff = (size_t)((u & 3) * 32);
            const uint32_t dst = bb + (uint32_t)plane * 16384 + (uint32_t)((u & 3) * 4096) + sw_base;
            const __nv_bfloat16* g;
            if (plane == 0)      g = Ah + aoff + roff * lda + k0;
            else if (plane == 1) g = Al + aoff + roff * lda + k0;
            else if (plane == 2) g = Wh + woff + roff * ldw + k0;
            else                 g = Wl + woff + roff * ldw + k0;
            cp16(dst, g);
        }
    };

    const int l7 = lane & 7;
    const uint32_t xorv = (uint32_t)l7 << 4;
    const int a_row = wm * 64 + l7 + ((lane >> 3) & 1) * 8;
    const uint32_t a_kb = (uint32_t)((lane >> 4) & 1) * 16;
    const int b_row = wn * 32 + ((lane >> 4) & 1) * 8 + l7;
    const uint32_t b_kb = (uint32_t)((lane >> 3) & 1) * 16;

    float acc[4][4][4];
    #pragma unroll
    for (int i = 0; i < 4; i++)
        #pragma unroll
        for (int j = 0; j < 4; j++)
            #pragma unroll
            for (int r = 0; r < 4; r++) acc[i][j][r] = 0.f;

    const int nt = K / 64;

    fill(0, 0);
    CP_COMMIT();

    for (int t = 0; t < nt; t++) {
        const int buf = t & 1;
        if (t + 1 < nt) {
            fill(buf ^ 1, (t + 1) * 64);
            CP_COMMIT();
            CP_WAIT(1);
        } else {
            CP_WAIT(0);
        }
        __syncthreads();

        const uint32_t bb = sbase + (uint32_t)buf * 65536;
        #pragma unroll
        for (int kk = 0; kk < 4; kk++) {
            const uint32_t koff_a = ((uint32_t)(kk * 32) + a_kb) ^ xorv;
            const uint32_t koff_b = ((uint32_t)(kk * 32) + b_kb) ^ xorv;
            uint32_t ah[4][4], al[4][4], bh[2][4], bl[2][4];
            #pragma unroll
            for (int i = 0; i < 4; i++) {
                uint32_t ad = bb + (uint32_t)((a_row + i * 16) * 128) + koff_a;
                ldsm_x4(ah[i], ad);
                ldsm_x4(al[i], ad + 16384);
            }
            #pragma unroll
            for (int jj = 0; jj < 2; jj++) {
                uint32_t bd = bb + 32768 + (uint32_t)((b_row + jj * 16) * 128) + koff_b;
                ldsm_x4(bh[jj], bd);
                ldsm_x4(bl[jj], bd + 16384);
            }
            // term-major: 16 independent MMAs per pass, acc reuse distance = 16
            #pragma unroll
            for (int i = 0; i < 4; i++)
                #pragma unroll
                for (int j = 0; j < 4; j++)
                    mma16816(acc[i][j], ah[i], &bh[j >> 1][(j & 1) * 2]);
            #pragma unroll
            for (int i = 0; i < 4; i++)
                #pragma unroll
                for (int j = 0; j < 4; j++)
                    mma16816(acc[i][j], ah[i], &bl[j >> 1][(j & 1) * 2]);
            #pragma unroll
            for (int i = 0; i < 4; i++)
                #pragma unroll
                for (int j = 0; j < 4; j++)
                    mma16816(acc[i][j], al[i], &bh[j >> 1][(j & 1) * 2]);
        }
        __syncthreads();
    }

    // ---- epilogue
    const int g = lane >> 2;
    const int t4 = lane & 3;
    #pragma unroll
    for (int i = 0; i < 4; i++) {
        const int r0 = bm + wm * 64 + i * 16 + g;
        const int r1 = r0 + 8;
        #pragma unroll
        for (int j = 0; j < 4; j++) {
            const int col = bn + wn * 32 + j * 8 + t4 * 2;
            const float b0 = bias ? __ldg(&bias[col]) : 0.f;
            const float b1 = bias ? __ldg(&bias[col + 1]) : 0.f;
            float2 v0 = make_float2(acc[i][j][0] + b0, acc[i][j][1] + b1);
            float2 v1 = make_float2(acc[i][j][2] + b0, acc[i][j][3] + b1);
            if (C) {
                *reinterpret_cast<float2*>(&C[(size_t)r0 * N + col]) = v0;
                *reinterpret_cast<float2*>(&C[(size_t)r1 * N + col]) = v1;
            }
            if (Ch) {
                __nv_bfloat162 h0 = __floats2bfloat162_rn(v0.x, v0.y);
                __nv_bfloat162 h1 = __floats2bfloat162_rn(v1.x, v1.y);
                __nv_bfloat162 l0 = __floats2bfloat162_rn(v0.x - __bfloat162float(h0.x),
                                                          v0.y - __bfloat162float(h0.y));
                __nv_bfloat162 l1 = __floats2bfloat162_rn(v1.x - __bfloat162float(h1.x),
                                                          v1.y - __bfloat162float(h1.y));
                *reinterpret_cast<uint32_t*>(&Ch[(size_t)r0 * N + col]) = bf2_bits(h0);
                *reinterpret_cast<uint32_t*>(&Ch[(size_t)r1 * N + col]) = bf2_bits(h1);
                *reinterpret_cast<uint32_t*>(&Cl[(size_t)r0 * N + col]) = bf2_bits(l0);
                *reinterpret_cast<uint32_t*>(&Cl[(size_t)r1 * N + col]) = bf2_bits(l1);
            }
        }
    }
}

// =====================================================================
// SIMT GEMM (x_proj split-K, dt_proj)
// =====================================================================
#define GBM 128
#define GBK 16

template<int BN>
__global__ __launch_bounds__(256) void gemm_nt(
    const float* __restrict__ A, int lda,
    const float* __restrict__ W, int ldw,
    const float* __restrict__ bias, float* __restrict__ C,
    int M, int N, int K, int act)
{
    constexpr int TN = BN / 16;
    constexpr int WU = (BN * 4) / 256;

    __shared__ float As[2][GBK][GBM];
    __shared__ float Ws[2][GBK][BN];

    const int z = blockIdx.z;
    A += (size_t)z * K;
    W += (size_t)z * K;
    C += (size_t)z * M * N;

    const int bm = blockIdx.y * GBM;
    const int bn = blockIdx.x * BN;
    const int tid = threadIdx.x;
    const int tr = tid >> 4;
    const int tc = tid & 15;

    float acc[8][TN];
    #pragma unroll
    for (int i = 0; i < 8; i++)
        #pragma unroll
        for (int j = 0; j < TN; j++) acc[i][j] = 0.f;

    float4 ra[2], rw[WU];
    int ai[2], aj[2], wi[WU], wj[WU];
    #pragma unroll
    for (int u = 0; u < 2; u++) { int s = tid + u * 256; ai[u] = s >> 2; aj[u] = (s & 3) << 2; }
    #pragma unroll
    for (int u = 0; u < WU; u++) { int s = tid + u * 256; wi[u] = s >> 2; wj[u] = (s & 3) << 2; }

    const int nt = K / GBK;

    #pragma unroll
    for (int u = 0; u < 2; u++)
        ra[u] = *reinterpret_cast<const float4*>(&A[(size_t)(bm + ai[u]) * lda + aj[u]]);
    #pragma unroll
    for (int u = 0; u < WU; u++)
        rw[u] = *reinterpret_cast<const float4*>(&W[(size_t)(bn + wi[u]) * ldw + wj[u]]);
    #pragma unroll
    for (int u = 0; u < 2; u++) {
        As[0][aj[u] + 0][ai[u]] = ra[u].x; As[0][aj[u] + 1][ai[u]] = ra[u].y;
        As[0][aj[u] + 2][ai[u]] = ra[u].z; As[0][aj[u] + 3][ai[u]] = ra[u].w;
    }
    #pragma unroll
    for (int u = 0; u < WU; u++) {
        Ws[0][wj[u] + 0][wi[u]] = rw[u].x; Ws[0][wj[u] + 1][wi[u]] = rw[u].y;
        Ws[0][wj[u] + 2][wi[u]] = rw[u].z; Ws[0][wj[u] + 3][wi[u]] = rw[u].w;
    }
    __syncthreads();

    for (int t = 0; t < nt; t++) {
        const int buf = t & 1;
        const bool more = (t + 1 < nt);
        if (more) {
            const int k0 = (t + 1) * GBK;
            #pragma unroll
            for (int u = 0; u < 2; u++)
                ra[u] = *reinterpret_cast<const float4*>(&A[(size_t)(bm + ai[u]) * lda + k0 + aj[u]]);
            #pragma unroll
            for (int u = 0; u < WU; u++)
                rw[u] = *reinterpret_cast<const float4*>(&W[(size_t)(bn + wi[u]) * ldw + k0 + wj[u]]);
        }

        #pragma unroll
        for (int k = 0; k < GBK; k++) {
            float a[8], w[TN];
            float4 a0 = *reinterpret_cast<const float4*>(&As[buf][k][tr * 8]);
            float4 a1 = *reinterpret_cast<const float4*>(&As[buf][k][tr * 8 + 4]);
            a[0]=a0.x; a[1]=a0.y; a[2]=a0.z; a[3]=a0.w;
            a[4]=a1.x; a[5]=a1.y; a[6]=a1.z; a[7]=a1.w;
            #pragma unroll
            for (int j4 = 0; j4 < TN; j4 += 4) {
                float4 w0 = *reinterpret_cast<const float4*>(&Ws[buf][k][tc * TN + j4]);
                w[j4+0]=w0.x; w[j4+1]=w0.y; w[j4+2]=w0.z; w[j4+3]=w0.w;
            }
            #pragma unroll
            for (int i = 0; i < 8; i++)
                #pragma unroll
                for (int j = 0; j < TN; j++)
                    acc[i][j] = fmaf(a[i], w[j], acc[i][j]);
        }

        if (more) {
            const int nbuf = buf ^ 1;
            #pragma unroll
            for (int u = 0; u < 2; u++) {
                As[nbuf][aj[u] + 0][ai[u]] = ra[u].x; As[nbuf][aj[u] + 1][ai[u]] = ra[u].y;
                As[nbuf][aj[u] + 2][ai[u]] = ra[u].z; As[nbuf][aj[u] + 3][ai[u]] = ra[u].w;
            }
            #pragma unroll
            for (int u = 0; u < WU; u++) {
                Ws[nbuf][wj[u] + 0][wi[u]] = rw[u].x; Ws[nbuf][wj[u] + 1][wi[u]] = rw[u].y;
                Ws[nbuf][wj[u] + 2][wi[u]] = rw[u].z; Ws[nbuf][wj[u] + 3][wi[u]] = rw[u].w;
            }
        }
        __syncthreads();
    }

    float bfrag[TN];
    #pragma unroll
    for (int j = 0; j < TN; j++)
        bfrag[j] = bias ? __ldg(&bias[bn + tc * TN + j]) : 0.f;

    #pragma unroll
    for (int i = 0; i < 8; i++) {
        const size_t row = bm + tr * 8 + i;
        #pragma unroll
        for (int j4 = 0; j4 < TN; j4 += 4) {
            float4 v;
            float* vv = &v.x;
            #pragma unroll
            for (int j = 0; j < 4; j++) {
                float u = acc[i][j4 + j] + bfrag[j4 + j];
                if (act == 1) u = act_softplus(u);
                vv[j] = u;
            }
            *reinterpret_cast<float4*>(&C[row * N + bn + tc * TN + j4]) = v;
        }
    }
}

__global__ void reduce_ksplit(const float* __restrict__ part, float* __restrict__ out, int n)
{
    int i = blockIdx.x * blockDim.x + threadIdx.x;
    if (i >= n) return;
    float acc = 0.f;
    #pragma unroll
    for (int zz = 0; zz < KSPLIT; zz++) acc += part[(size_t)zz * n + i];
    out[i] = acc;
}

// ---------------- causal depthwise conv1d + bias + SiLU ----------------
__global__ void conv_silu_kernel(const float* __restrict__ xz,
                                 const float* __restrict__ cw,
                                 const float* __restrict__ cb,
                                 float* __restrict__ xc)
{
    int idx = blockIdx.x * blockDim.x + threadIdx.x;
    if (idx >= ML * D_INNER) return;
    int d = idx & (D_INNER - 1);
    int bl = idx >> 10;
    int l = bl & (L_ - 1);
    int b = bl >> 9;

    float w0 = __ldg(&cw[d * 4 + 0]);
    float w1 = __ldg(&cw[d * 4 + 1]);
    float w2 = __ldg(&cw[d * 4 + 2]);
    float w3 = __ldg(&cw[d * 4 + 3]);
    float acc = __ldg(&cb[d]);

    const size_t rowstride = 2 * D_INNER;
    size_t base = ((size_t)b * L_) * rowstride + d;
    if (l >= 3) acc = fmaf(w0, xz[base + (size_t)(l - 3) * rowstride], acc);
    if (l >= 2) acc = fmaf(w1, xz[base + (size_t)(l - 2) * rowstride], acc);
    if (l >= 1) acc = fmaf(w2, xz[base + (size_t)(l - 1) * rowstride], acc);
    acc = fmaf(w3, xz[base + (size_t)l * rowstride], acc);

    xc[idx] = act_silu(acc);
}

// ---------------- selective scan (emits y as bf16 hi/lo planes) ----------------
__global__ __launch_bounds__(64) void scan_kernel(
    const float* __restrict__ dt, const float* __restrict__ xc,
    const float* __restrict__ xdbl, const float* __restrict__ xz,
    const float* __restrict__ A_log, const float* __restrict__ Dm,
    __nv_bfloat16* __restrict__ yh, __nv_bfloat16* __restrict__ yl)
{
    const int tid = threadIdx.x;
    const int d = blockIdx.x * 64 + tid;
    const int b = blockIdx.y;

    __shared__ float sBC[2][8][32];

    float Av[D_STATE];
    #pragma unroll
    for (int s = 0; s < D_STATE; s++) Av[s] = -__expf(__ldg(&A_log[d * D_STATE + s]));
    const float Av0 = Av[0];
    int fastl = 1;
    #pragma unroll
    for (int s = 1; s < D_STATE; s++) {
        float tgt = (s + 1) * Av0;
        fastl &= (fabsf(Av[s] - tgt) <= 1e-4f * fabsf(tgt)) ? 1 : 0;
    }
    const int fast = __syncthreads_and(fastl);

    float h[D_STATE];
    #pragma unroll
    for (int s = 0; s < D_STATE; s++) h[s] = 0.f;
    const float Dd = __ldg(&Dm[d]);
    const size_t rowb = (size_t)b * L_;

    float cdt[8], cxc[8], cz[8], ndt[8], nxc[8], nz[8];

    {
        int r = tid >> 3, q = tid & 7;
        float4 v = *reinterpret_cast<const float4*>(&xdbl[(rowb + r) * 64 + 32 + q * 4]);
        *reinterpret_cast<float4*>(&sBC[0][r][q * 4]) = v;
    }
    #pragma unroll
    for (int i = 0; i < 8; i++) {
        size_t row = rowb + i;
        cdt[i] = __ldg(&dt[row * D_INNER + d]);
        cxc[i] = __ldg(&xc[row * D_INNER + d]);
        cz[i]  = __ldg(&xz[row * 2 * D_INNER + D_INNER + d]);
    }
    __syncthreads();

    for (int w = 0; w < L_ / 8; w++) {
        const int slot = w & 1;
        if (w + 1 < L_ / 8) {
            int r = tid >> 3, q = tid & 7;
            float4 v = *reinterpret_cast<const float4*>(
                &xdbl[(rowb + (w + 1) * 8 + r) * 64 + 32 + q * 4]);
            *reinterpret_cast<float4*>(&sBC[slot ^ 1][r][q * 4]) = v;
            #pragma unroll
            for (int i = 0; i < 8; i++) {
                size_t row = rowb + (w + 1) * 8 + i;
                ndt[i] = __ldg(&dt[row * D_INNER + d]);
                nxc[i] = __ldg(&xc[row * D_INNER + d]);
                nz[i]  = __ldg(&xz[row * 2 * D_INNER + D_INNER + d]);
            }
        }

        #pragma unroll
        for (int i = 0; i < 8; i++) {
            const float dtv = cdt[i], xv = cxc[i], zv = cz[i];
            const float p = dtv * xv;
            const float* bc = sBC[slot][i];
            float acc0 = 0.f, acc1 = 0.f;
            if (fast) {
                const float q1 = __expf(dtv * Av0);
                const float q2 = q1 * q1, q3 = q2 * q1, q4 = q2 * q2;
                const float q5 = q4 * q1, q6 = q4 * q2, q7 = q4 * q3, q8 = q4 * q4;
                const float dA[16] = {q1, q2, q3, q4, q5, q6, q7, q8,
                                      q8*q1, q8*q2, q8*q3, q8*q4, q8*q5, q8*q6, q8*q7, q8*q8};
                #pragma unroll
                for (int s = 0; s < D_STATE; s++) {
                    float hs = fmaf(dA[s], h[s], p * bc[s]);
                    h[s] = hs;
                    if (s & 1) acc1 = fmaf(hs, bc[16 + s], acc1);
                    else       acc0 = fmaf(hs, bc[16 + s], acc0);
                }
            } else {
                #pragma unroll
                for (int s = 0; s < D_STATE; s++) {
                    float hs = fmaf(__expf(dtv * Av[s]), h[s], p * bc[s]);
                    h[s] = hs;
                    if (s & 1) acc1 = fmaf(hs, bc[16 + s], acc1);
                    else       acc0 = fmaf(hs, bc[16 + s], acc0);
                }
            }
            const size_t row = rowb + w * 8 + i;
            float yv = fmaf(xv, Dd, acc0 + acc1) * act_silu(zv);
            __nv_bfloat16 hh = __float2bfloat16(yv);
            yh[row * D_INNER + d] = hh;
            yl[row * D_INNER + d] = __float2bfloat16(yv - __bfloat162float(hh));
        }

        #pragma unroll
        for (int i = 0; i < 8; i++) { cdt[i] = ndt[i]; cxc[i] = nxc[i]; cz[i] = nz[i]; }
        __syncthreads();
    }
}

// ---------------- mean over L (2-stage) ----------------
__global__ void mean_part_kernel(const float* __restrict__ h, float* __restrict__ part)
{
    int b = blockIdx.x, lc = blockIdx.y, d = threadIdx.x;
    float acc = 0.f;
    #pragma unroll 8
    for (int l = lc * 64; l < lc * 64 + 64; l++)
        acc += h[((size_t)b * L_ + l) * D_MODEL + d];
    part[(b * 8 + lc) * D_MODEL + d] = acc;
}
__global__ void mean_fin_kernel(const float* __restrict__ part, float* __restrict__ hm)
{
    int i = blockIdx.x * blockDim.x + threadIdx.x;
    if (i >= B_ * D_MODEL) return;
    int b = i / D_MODEL, d = i % D_MODEL;
    float acc = 0.f;
    #pragma unroll
    for (int c = 0; c < 8; c++) acc += part[(b * 8 + c) * D_MODEL + d];
    hm[i] = acc * (1.f / L_);
}

// ---------------- classifier head ----------------
__global__ void cls_kernel(const float* __restrict__ hm,
                           const float* __restrict__ w1, const float* __restrict__ b1,
                           const float* __restrict__ w2, const float* __restrict__ b2,
                           float* __restrict__ out)
{
    int b = blockIdx.x;
    int j = threadIdx.x;
    __shared__ float sh[64];
    float acc = __ldg(&b1[j]);
    const float* hv = hm + b * D_MODEL;
    const float* wv = w1 + j * D_MODEL;
    for (int k = 0; k < D_MODEL; k += 4) {
        float4 hh = *reinterpret_cast<const float4*>(&hv[k]);
        float4 ww = *reinterpret_cast<const float4*>(&wv[k]);
        acc = fmaf(hh.x, ww.x, acc);
        acc = fmaf(hh.y, ww.y, acc);
        acc = fmaf(hh.z, ww.z, acc);
        acc = fmaf(hh.w, ww.w, acc);
    }
    acc = fmaxf(acc, 0.f);
    sh[j] = acc * __ldg(&w2[j]);
    __syncthreads();
    if (j == 0) {
        float s = __ldg(&b2[0]);
        #pragma unroll
        for (int t = 0; t < 64; t++) s += sh[t];
        out[b] = s;
    }
}

// ---------------- launch ----------------
extern "C" void kernel_launch(void* const* d_in, const int* in_sizes, int n_in,
                              void* d_out, int out_size)
{
    const float* x          = (const float*)d_in[0];
    const float* proj_in_w  = (const float*)d_in[1];
    const float* proj_in_b  = (const float*)d_in[2];
    const float* in_proj_w  = (const float*)d_in[3];
    const float* conv_w     = (const float*)d_in[4];
    const float* conv_b     = (const float*)d_in[5];
    const float* x_proj_w   = (const float*)d_in[6];
    const float* dt_proj_w  = (const float*)d_in[7];
    const float* dt_proj_b  = (const float*)d_in[8];
    const float* A_log      = (const float*)d_in[9];
    const float* Dm         = (const float*)d_in[10];
    const float* out_proj_w = (const float*)d_in[11];
    const float* cls_w1     = (const float*)d_in[12];
    const float* cls_b1     = (const float*)d_in[13];
    const float* cls_w2     = (const float*)d_in[14];
    const float* cls_b2     = (const float*)d_in[15];

    void* p;
    cudaGetSymbolAddress(&p, g_ha);    float* ha    = (float*)p;
    cudaGetSymbolAddress(&p, g_xz);    float* xz    = (float*)p;
    cudaGetSymbolAddress(&p, g_xc);    float* xc    = (float*)p;
    cudaGetSymbolAddress(&p, g_xdbl);  float* xdbl  = (float*)p;
    cudaGetSymbolAddress(&p, g_xpart); float* xpart = (float*)p;
    cudaGetSymbolAddress(&p, g_dt);    float* dtb   = (float*)p;
    cudaGetSymbolAddress(&p, g_hpart); float* hpart = (float*)p;
    cudaGetSymbolAddress(&p, g_hm);    float* hm    = (float*)p;

    __nv_bfloat16 *xh, *xl, *piwh, *piwl, *inwh, *inwl, *outwh, *outwl, *hh, *hl, *yh, *yl;
    cudaGetSymbolAddress(&p, g_xh);    xh    = (__nv_bfloat16*)p;
    cudaGetSymbolAddress(&p, g_xl);    xl    = (__nv_bfloat16*)p;
    cudaGetSymbolAddress(&p, g_piwh);  piwh  = (__nv_bfloat16*)p;
    cudaGetSymbolAddress(&p, g_piwl);  piwl  = (__nv_bfloat16*)p;
    cudaGetSymbolAddress(&p, g_inwh);  inwh  = (__nv_bfloat16*)p;
    cudaGetSymbolAddress(&p, g_inwl);  inwl  = (__nv_bfloat16*)p;
    cudaGetSymbolAddress(&p, g_outwh); outwh = (__nv_bfloat16*)p;
    cudaGetSymbolAddress(&p, g_outwl); outwl = (__nv_bfloat16*)p;
    cudaGetSymbolAddress(&p, g_hh);    hh    = (__nv_bfloat16*)p;
    cudaGetSymbolAddress(&p, g_hl);    hl    = (__nv_bfloat16*)p;
    cudaGetSymbolAddress(&p, g_yh);    yh    = (__nv_bfloat16*)p;
    cudaGetSymbolAddress(&p, g_yl);    yl    = (__nv_bfloat16*)p;

    cudaFuncSetAttribute(gemm_mma, cudaFuncAttributeMaxDynamicSharedMemorySize, MMA_SMEM_BYTES);

    // ---- launch 1: cvt x + proj_in_w ; launch 2: cvt in_proj_w + out_proj_w
    {
        int n0 = ML * D_IN / 4, n1 = D_MODEL * D_IN / 4;
        cvt_split2<<<(n0 + n1 + 255) / 256, 256>>>(x, xh, xl, n0, proj_in_w, piwh, piwl, n1);
    }
    {
        int n0 = N_LAYERS * 2 * D_INNER * D_MODEL / 4, n1 = N_LAYERS * D_MODEL * D_INNER / 4;
        cvt_split2<<<(n0 + n1 + 255) / 256, 256>>>(in_proj_w, inwh, inwl, n0,
                                                   out_proj_w, outwh, outwl, n1);
    }

    // launch 3: h = x @ proj_in_w^T + b  -> h planes
    gemm_mma<<<dim3(D_MODEL / 128, ML / 128), 256, MMA_SMEM_BYTES>>>(
        xh, xl, D_IN, piwh, piwl, D_IN, proj_in_b, nullptr, hh, hl, D_MODEL, D_IN);

    for (int l = 0; l < N_LAYERS; l++) {
        const size_t inw_off  = (size_t)l * 2 * D_INNER * D_MODEL;
        const size_t outw_off = (size_t)l * D_MODEL * D_INNER;
        const float* cw    = conv_w     + (size_t)l * D_INNER * D_CONV;
        const float* cb    = conv_b     + (size_t)l * D_INNER;
        const float* xp_w  = x_proj_w   + (size_t)l * 64 * D_INNER;
        const float* dt_w  = dt_proj_w  + (size_t)l * D_INNER * DT_RANK;
        const float* dt_b  = dt_proj_b  + (size_t)l * D_INNER;
        const float* Al    = A_log      + (size_t)l * D_INNER * D_STATE;
        const float* Dl    = Dm         + (size_t)l * D_INNER;
        const bool last = (l == N_LAYERS - 1);

        // launch 4 (layer 0): xz = h @ in_w^T  -- profiled launch
        gemm_mma<<<dim3(2 * D_INNER / 128, ML / 128), 256, MMA_SMEM_BYTES>>>(
            hh, hl, D_MODEL, inwh + inw_off, inwl + inw_off, D_MODEL,
            nullptr, xz, nullptr, nullptr, 2 * D_INNER, D_MODEL);
        conv_silu_kernel<<<(ML * D_INNER) / 256, 256>>>(xz, cw, cb, xc);
        gemm_nt<64><<<dim3(1, ML / GBM, KSPLIT), 256>>>(
            xc, D_INNER, xp_w, D_INNER, nullptr, xpart, ML, 64, D_INNER / KSPLIT, 0);
        reduce_ksplit<<<(ML * 64 + 255) / 256, 256>>>(xpart, xdbl, ML * 64);
        gemm_nt<128><<<dim3(D_INNER / 128, ML / GBM), 256>>>(
            xdbl, 64, dt_w, DT_RANK, dt_b, dtb, ML, D_INNER, DT_RANK, 1);
        scan_kernel<<<dim3(D_INNER / 64, B_), 64>>>(dtb, xc, xdbl, xz, Al, Dl, yh, yl);
        gemm_mma<<<dim3(D_MODEL / 128, ML / 128), 256, MMA_SMEM_BYTES>>>(
            yh, yl, D_INNER, outwh + outw_off, outwl + outw_off, D_INNER,
            nullptr, last ? ha : nullptr, last ? nullptr : hh, last ? nullptr : hl,
            D_MODEL, D_INNER);
    }

    mean_part_kernel<<<dim3(B_, 8), D_MODEL>>>(ha, hpart);
    mean_fin_kernel<<<(B_ * D_MODEL + 255) / 256, 256>>>(hpart, hm);
    cls_kernel<<<B_, 64>>>(hm, cls_w1, cls_b1, cls_w2, cls_b2, (float*)d_out);
}